// round 1
// baseline (speedup 1.0000x reference)
#include <cuda_runtime.h>
#include <cuda_bf16.h>

// Problem constants
#define BB 4
#define SS 2048
#define HH 512
#define NHH 8
#define HDD 64

// Scratch (device globals: no allocation allowed in kernel_launch)
__device__ float g_Q[BB * SS * HH];
__device__ float g_K[BB * SS * HH];
__device__ float g_V[BB * SS * HH];
__device__ float g_C[BB * SS * HH];

// ---------------------------------------------------------------------------
// Templated SGEMM.
//   BT = true : C[m,n] = alpha * sum_k A[m*lda+k] * B[n*ldb+k] (+bias[n])
//   BT = false: C[m,n] = alpha * sum_k A[m*lda+k] * B[k*ldb+n] (+bias[n])
// Batch offset: z = blockIdx.z, decomposed as (b = z/NH, h = z%NH):
//   ptr += b*stride_b + h*stride_h  for each of A, B, C.
// ---------------------------------------------------------------------------
template <int BM, int BN, int BK, int TM, int TN, bool BT>
__global__ __launch_bounds__((BM / TM) * (BN / TN))
void gemm_kernel(const float* __restrict__ A,
                 const float* __restrict__ Bm,
                 const float* __restrict__ bias,
                 float* __restrict__ C,
                 int K, int lda, int ldb, int ldc,
                 long long sAb, long long sAh,
                 long long sBb, long long sBh,
                 long long sCb, long long sCh,
                 float alpha)
{
    constexpr int THREADS = (BM / TM) * (BN / TN);
    __shared__ float As[BK][BM + 4];
    __shared__ float Bs[BK][BN + 4];

    const int z = blockIdx.z;
    const int zb = z / NHH;
    const int zh = z % NHH;
    A  += zb * sAb + zh * sAh;
    Bm += zb * sBb + zh * sBh;
    C  += zb * sCb + zh * sCh;

    const int bm = blockIdx.y * BM;
    const int bn = blockIdx.x * BN;
    const int tid = threadIdx.x;
    const int tnx = tid % (BN / TN);
    const int tmy = tid / (BN / TN);

    float acc[TM][TN];
#pragma unroll
    for (int i = 0; i < TM; i++)
#pragma unroll
        for (int j = 0; j < TN; j++) acc[i][j] = 0.0f;

    constexpr int A_ITERS = (BM * BK) / (THREADS * 4);
    constexpr int B_ITERS = (BN * BK) / (THREADS * 4);

    for (int k0 = 0; k0 < K; k0 += BK) {
        // --- load A tile (BM x BK), store transposed: As[k][m] ---
#pragma unroll
        for (int it = 0; it < A_ITERS; it++) {
            int e = tid * 4 + it * THREADS * 4;
            int m = e / BK;
            int kk = e % BK;
            float4 v = *(const float4*)(A + (long long)(bm + m) * lda + k0 + kk);
            As[kk + 0][m] = v.x;
            As[kk + 1][m] = v.y;
            As[kk + 2][m] = v.z;
            As[kk + 3][m] = v.w;
        }
        // --- load B tile ---
        if (BT) {
#pragma unroll
            for (int it = 0; it < B_ITERS; it++) {
                int e = tid * 4 + it * THREADS * 4;
                int n = e / BK;
                int kk = e % BK;
                float4 v = *(const float4*)(Bm + (long long)(bn + n) * ldb + k0 + kk);
                Bs[kk + 0][n] = v.x;
                Bs[kk + 1][n] = v.y;
                Bs[kk + 2][n] = v.z;
                Bs[kk + 3][n] = v.w;
            }
        } else {
#pragma unroll
            for (int it = 0; it < B_ITERS; it++) {
                int e = tid * 4 + it * THREADS * 4;
                int kk = e / BN;
                int n = e % BN;
                float4 v = *(const float4*)(Bm + (long long)(k0 + kk) * ldb + bn + n);
                *(float4*)&Bs[kk][n] = v;
            }
        }
        __syncthreads();

#pragma unroll
        for (int kk = 0; kk < BK; kk++) {
            float a[TM], b[TN];
#pragma unroll
            for (int i = 0; i < TM; i += 4)
                *(float4*)&a[i] = *(const float4*)&As[kk][tmy * TM + i];
#pragma unroll
            for (int j = 0; j < TN; j += 4)
                *(float4*)&b[j] = *(const float4*)&Bs[kk][tnx * TN + j];
#pragma unroll
            for (int i = 0; i < TM; i++)
#pragma unroll
                for (int j = 0; j < TN; j++)
                    acc[i][j] += a[i] * b[j];
        }
        __syncthreads();
    }

    // epilogue
#pragma unroll
    for (int i = 0; i < TM; i++) {
        long long row = bm + tmy * TM + i;
#pragma unroll
        for (int j = 0; j < TN; j += 4) {
            int col = bn + tnx * TN + j;
            float4 o;
            o.x = alpha * acc[i][j + 0] + (bias ? bias[col + 0] : 0.0f);
            o.y = alpha * acc[i][j + 1] + (bias ? bias[col + 1] : 0.0f);
            o.z = alpha * acc[i][j + 2] + (bias ? bias[col + 2] : 0.0f);
            o.w = alpha * acc[i][j + 3] + (bias ? bias[col + 3] : 0.0f);
            *(float4*)(C + row * ldc + col) = o;
        }
    }
}

// ---------------------------------------------------------------------------
// In-place row softmax over last dim (row length SS=2048). One block per row.
// ---------------------------------------------------------------------------
__global__ __launch_bounds__(256) void softmax_kernel(float* __restrict__ attn)
{
    __shared__ float red[8];
    const long long row = blockIdx.x;
    float* p = attn + row * (long long)SS;
    const int tid = threadIdx.x;
    const int lane = tid & 31;
    const int wid = tid >> 5;

    float v[8];
    *(float4*)&v[0] = *(const float4*)(p + tid * 8);
    *(float4*)&v[4] = *(const float4*)(p + tid * 8 + 4);

    float m = v[0];
#pragma unroll
    for (int i = 1; i < 8; i++) m = fmaxf(m, v[i]);
#pragma unroll
    for (int o = 16; o > 0; o >>= 1) m = fmaxf(m, __shfl_xor_sync(0xffffffffu, m, o));
    if (lane == 0) red[wid] = m;
    __syncthreads();
    float rowmax = red[0];
#pragma unroll
    for (int i = 1; i < 8; i++) rowmax = fmaxf(rowmax, red[i]);
    __syncthreads();

    float s = 0.0f;
#pragma unroll
    for (int i = 0; i < 8; i++) {
        v[i] = __expf(v[i] - rowmax);
        s += v[i];
    }
#pragma unroll
    for (int o = 16; o > 0; o >>= 1) s += __shfl_xor_sync(0xffffffffu, s, o);
    if (lane == 0) red[wid] = s;
    __syncthreads();
    float rowsum = 0.0f;
#pragma unroll
    for (int i = 0; i < 8; i++) rowsum += red[i];
    float inv = 1.0f / rowsum;

#pragma unroll
    for (int i = 0; i < 8; i++) v[i] *= inv;
    *(float4*)(p + tid * 8) = *(const float4*)&v[0];
    *(float4*)(p + tid * 8 + 4) = *(const float4*)&v[4];
}

// ---------------------------------------------------------------------------
extern "C" void kernel_launch(void* const* d_in, const int* in_sizes, int n_in,
                              void* d_out, int out_size)
{
    const float* query  = (const float*)d_in[0];
    const float* key_in = (const float*)d_in[1];
    const float* value  = (const float*)d_in[2];
    const float* Wq = (const float*)d_in[3];
    const float* bq = (const float*)d_in[4];
    const float* Wk = (const float*)d_in[5];
    const float* bk = (const float*)d_in[6];
    const float* Wv = (const float*)d_in[7];
    const float* bv = (const float*)d_in[8];
    const float* Wo = (const float*)d_in[9];
    const float* bo = (const float*)d_in[10];

    float* out  = (float*)d_out;                              // [B,S,H]
    float* attn = out + (long long)BB * SS * HH;              // [B,NH,S,S]

    float* Q;  cudaGetSymbolAddress((void**)&Q,  g_Q);
    float* Kb; cudaGetSymbolAddress((void**)&Kb, g_K);
    float* V;  cudaGetSymbolAddress((void**)&V,  g_V);
    float* Cx; cudaGetSymbolAddress((void**)&Cx, g_C);

    const int M = BB * SS;   // 8192

    dim3 blk(256);

    // --- projections: Y = X @ W^T + b ---
    {
        dim3 grid(HH / 64, M / 128, 1);
        gemm_kernel<128, 64, 16, 8, 4, true><<<grid, blk>>>(
            query, Wq, bq, Q, HH, HH, HH, HH, 0, 0, 0, 0, 0, 0, 1.0f);
        gemm_kernel<128, 64, 16, 8, 4, true><<<grid, blk>>>(
            key_in, Wk, bk, Kb, HH, HH, HH, HH, 0, 0, 0, 0, 0, 0, 1.0f);
        gemm_kernel<128, 64, 16, 8, 4, true><<<grid, blk>>>(
            value, Wv, bv, V, HH, HH, HH, HH, 0, 0, 0, 0, 0, 0, 1.0f);
    }

    // --- scores: attn[b,h,q,k] = scale * sum_d Q[b,q,h*HD+d] * K[b,k,h*HD+d] ---
    {
        dim3 grid(SS / 64, SS / 128, BB * NHH);
        const long long sQb = (long long)SS * HH, sQh = HDD;
        const long long sCb = (long long)NHH * SS * SS, sCh = (long long)SS * SS;
        gemm_kernel<128, 64, 16, 8, 4, true><<<grid, blk>>>(
            Q, Kb, nullptr, attn, HDD, HH, HH, SS,
            sQb, sQh, sQb, sQh, sCb, sCh, 0.125f);
    }

    // --- softmax rows ---
    softmax_kernel<<<BB * NHH * SS, 256>>>(attn);

    // --- context: Cx[b,q,h*HD+d] = sum_k attn[b,h,q,k] * V[b,k,h*HD+d] ---
    {
        dim3 grid(HDD / 64, SS / 128, BB * NHH);
        const long long sAb = (long long)NHH * SS * SS, sAh = (long long)SS * SS;
        const long long sVb = (long long)SS * HH, sVh = HDD;
        gemm_kernel<128, 64, 16, 8, 4, false><<<grid, blk>>>(
            attn, V, nullptr, Cx, SS, SS, HH, HH,
            sAb, sAh, sVb, sVh, sVb, sVh, 1.0f);
    }

    // --- output projection: out = Cx @ Wo^T + bo ---
    {
        dim3 grid(HH / 64, M / 128, 1);
        gemm_kernel<128, 64, 16, 8, 4, true><<<grid, blk>>>(
            Cx, Wo, bo, out, HH, HH, HH, HH, 0, 0, 0, 0, 0, 0, 1.0f);
    }
}

// round 2
// speedup vs baseline: 1.9871x; 1.9871x over previous
#include <cuda_runtime.h>
#include <cuda_bf16.h>

#define BB 4
#define SS 2048
#define HH 512
#define NHH 8
#define HDD 64

// Scratch (device globals: no allocation allowed in kernel_launch)
__device__ float g_Q[BB * SS * HH];
__device__ float g_K[BB * SS * HH];
__device__ float g_V[BB * SS * HH];
__device__ float g_C[BB * SS * HH];

__device__ __forceinline__ unsigned f2tf32(float x) {
    unsigned r;
    asm("cvt.rna.tf32.f32 %0, %1;" : "=r"(r) : "f"(x));
    return r;
}

__device__ __forceinline__ void mma_tf32(float& c0, float& c1, float& c2, float& c3,
                                         unsigned a0, unsigned a1, unsigned a2, unsigned a3,
                                         unsigned b0, unsigned b1) {
    asm volatile(
        "mma.sync.aligned.m16n8k8.row.col.f32.tf32.tf32.f32 "
        "{%0,%1,%2,%3}, {%4,%5,%6,%7}, {%8,%9}, {%0,%1,%2,%3};"
        : "+f"(c0), "+f"(c1), "+f"(c2), "+f"(c3)
        : "r"(a0), "r"(a1), "r"(a2), "r"(a3), "r"(b0), "r"(b1));
}

// ---------------------------------------------------------------------------
// Tensor-core tf32 GEMM.
//   BT = true : C[m,n] = alpha * sum_k A[m*lda+k] * B[n*ldb+k] (+bias[n])
//   BT = false: C[m,n] = alpha * sum_k A[m*lda+k] * B[k*ldb+n] (+bias[n])
// Batched by blockIdx.z -> (b = z/NH, h = z%NH) with per-operand strides.
// ---------------------------------------------------------------------------
template <int BM, int BN, int BK, int WM, int WN, bool BT>
__global__ __launch_bounds__((BM / WM) * (BN / WN) * 32)
void gemm_tc(const float* __restrict__ A,
             const float* __restrict__ Bm,
             const float* __restrict__ bias,
             float* __restrict__ C,
             int K, int lda, int ldb, int ldc,
             long long sAb, long long sAh,
             long long sBb, long long sBh,
             long long sCb, long long sCh,
             float alpha)
{
    constexpr int NWN = BN / WN;
    constexpr int THREADS = (BM / WM) * (BN / WN) * 32;
    constexpr int MT = WM / 16;
    constexpr int NT = WN / 8;
    constexpr int SA = BK + 4;                    // 36: stride ≡ 4 (mod 32)
    constexpr int SB = BT ? (BK + 4) : (BN + 8);  // 36 or BN+8 (≡ 8 mod 32)

    __shared__ unsigned As[BM * SA];
    __shared__ unsigned Bs[(BT ? BN : BK) * SB];

    const int z = blockIdx.z;
    const int zb = z / NHH;
    const int zh = z % NHH;
    A  += zb * sAb + zh * sAh;
    Bm += zb * sBb + zh * sBh;
    C  += zb * sCb + zh * sCh;

    const int bm = blockIdx.y * BM;
    const int bn = blockIdx.x * BN;
    const int tid = threadIdx.x;
    const int warpId = tid >> 5;
    const int lane = tid & 31;
    const int g = lane >> 2;    // group id (0..7)
    const int tg = lane & 3;    // thread in group (0..3)
    const int wm = warpId / NWN;
    const int wn = warpId % NWN;

    float c[MT][NT][4];
#pragma unroll
    for (int i = 0; i < MT; i++)
#pragma unroll
        for (int j = 0; j < NT; j++)
#pragma unroll
            for (int r = 0; r < 4; r++) c[i][j][r] = 0.0f;

    constexpr int A_ITERS = (BM * BK) / (THREADS * 4);
    constexpr int B_ITERS = ((BT ? BN : BK) * (BT ? BK : BN)) / (THREADS * 4);

    for (int k0 = 0; k0 < K; k0 += BK) {
        // --- stage A tile: As[m][k], stride 36, rounded to tf32 ---
#pragma unroll
        for (int it = 0; it < A_ITERS; it++) {
            int e = it * THREADS * 4 + tid * 4;
            int m = e / BK;
            int kk = e % BK;
            float4 v = *(const float4*)(A + (long long)(bm + m) * lda + k0 + kk);
            uint4 u = make_uint4(f2tf32(v.x), f2tf32(v.y), f2tf32(v.z), f2tf32(v.w));
            *(uint4*)&As[m * SA + kk] = u;
        }
        // --- stage B tile ---
        if (BT) {
#pragma unroll
            for (int it = 0; it < B_ITERS; it++) {
                int e = it * THREADS * 4 + tid * 4;
                int n = e / BK;
                int kk = e % BK;
                float4 v = *(const float4*)(Bm + (long long)(bn + n) * ldb + k0 + kk);
                uint4 u = make_uint4(f2tf32(v.x), f2tf32(v.y), f2tf32(v.z), f2tf32(v.w));
                *(uint4*)&Bs[n * SB + kk] = u;
            }
        } else {
#pragma unroll
            for (int it = 0; it < B_ITERS; it++) {
                int e = it * THREADS * 4 + tid * 4;
                int kk = e / BN;
                int n = e % BN;
                float4 v = *(const float4*)(Bm + (long long)(k0 + kk) * ldb + bn + n);
                uint4 u = make_uint4(f2tf32(v.x), f2tf32(v.y), f2tf32(v.z), f2tf32(v.w));
                *(uint4*)&Bs[kk * SB + n] = u;
            }
        }
        __syncthreads();

        // --- compute: BK/8 k-steps of m16n8k8 ---
#pragma unroll
        for (int kt = 0; kt < BK / 8; kt++) {
            unsigned a[MT][4], b[NT][2];
#pragma unroll
            for (int mt = 0; mt < MT; mt++) {
                int row = wm * WM + mt * 16 + g;
                int kb = kt * 8 + tg;
                a[mt][0] = As[row * SA + kb];
                a[mt][1] = As[(row + 8) * SA + kb];
                a[mt][2] = As[row * SA + kb + 4];
                a[mt][3] = As[(row + 8) * SA + kb + 4];
            }
#pragma unroll
            for (int nt = 0; nt < NT; nt++) {
                int col = wn * WN + nt * 8 + g;
                int kb = kt * 8 + tg;
                if (BT) {
                    b[nt][0] = Bs[col * SB + kb];
                    b[nt][1] = Bs[col * SB + kb + 4];
                } else {
                    b[nt][0] = Bs[kb * SB + col];
                    b[nt][1] = Bs[(kb + 4) * SB + col];
                }
            }
#pragma unroll
            for (int mt = 0; mt < MT; mt++)
#pragma unroll
                for (int nt = 0; nt < NT; nt++)
                    mma_tf32(c[mt][nt][0], c[mt][nt][1], c[mt][nt][2], c[mt][nt][3],
                             a[mt][0], a[mt][1], a[mt][2], a[mt][3],
                             b[nt][0], b[nt][1]);
        }
        __syncthreads();
    }

    // --- epilogue ---
#pragma unroll
    for (int mt = 0; mt < MT; mt++) {
#pragma unroll
        for (int nt = 0; nt < NT; nt++) {
            int row = bm + wm * WM + mt * 16 + g;
            int col = bn + wn * WN + nt * 8 + 2 * tg;
            float bx = bias ? bias[col] : 0.0f;
            float by = bias ? bias[col + 1] : 0.0f;
            float2 o0 = make_float2(alpha * c[mt][nt][0] + bx, alpha * c[mt][nt][1] + by);
            float2 o1 = make_float2(alpha * c[mt][nt][2] + bx, alpha * c[mt][nt][3] + by);
            *(float2*)(C + (long long)row * ldc + col) = o0;
            *(float2*)(C + (long long)(row + 8) * ldc + col) = o1;
        }
    }
}

// ---------------------------------------------------------------------------
// In-place row softmax over last dim (row length SS=2048). One block per row.
// ---------------------------------------------------------------------------
__global__ __launch_bounds__(256) void softmax_kernel(float* __restrict__ attn)
{
    __shared__ float red[8];
    const long long row = blockIdx.x;
    float* p = attn + row * (long long)SS;
    const int tid = threadIdx.x;
    const int lane = tid & 31;
    const int wid = tid >> 5;

    float v[8];
    *(float4*)&v[0] = *(const float4*)(p + tid * 8);
    *(float4*)&v[4] = *(const float4*)(p + tid * 8 + 4);

    float m = v[0];
#pragma unroll
    for (int i = 1; i < 8; i++) m = fmaxf(m, v[i]);
#pragma unroll
    for (int o = 16; o > 0; o >>= 1) m = fmaxf(m, __shfl_xor_sync(0xffffffffu, m, o));
    if (lane == 0) red[wid] = m;
    __syncthreads();
    float rowmax = red[0];
#pragma unroll
    for (int i = 1; i < 8; i++) rowmax = fmaxf(rowmax, red[i]);
    __syncthreads();

    float s = 0.0f;
#pragma unroll
    for (int i = 0; i < 8; i++) {
        v[i] = __expf(v[i] - rowmax);
        s += v[i];
    }
#pragma unroll
    for (int o = 16; o > 0; o >>= 1) s += __shfl_xor_sync(0xffffffffu, s, o);
    if (lane == 0) red[wid] = s;
    __syncthreads();
    float rowsum = 0.0f;
#pragma unroll
    for (int i = 0; i < 8; i++) rowsum += red[i];
    float inv = 1.0f / rowsum;

#pragma unroll
    for (int i = 0; i < 8; i++) v[i] *= inv;
    *(float4*)(p + tid * 8) = *(const float4*)&v[0];
    *(float4*)(p + tid * 8 + 4) = *(const float4*)&v[4];
}

// ---------------------------------------------------------------------------
extern "C" void kernel_launch(void* const* d_in, const int* in_sizes, int n_in,
                              void* d_out, int out_size)
{
    const float* query  = (const float*)d_in[0];
    const float* key_in = (const float*)d_in[1];
    const float* value  = (const float*)d_in[2];
    const float* Wq = (const float*)d_in[3];
    const float* bq = (const float*)d_in[4];
    const float* Wk = (const float*)d_in[5];
    const float* bk = (const float*)d_in[6];
    const float* Wv = (const float*)d_in[7];
    const float* bv = (const float*)d_in[8];
    const float* Wo = (const float*)d_in[9];
    const float* bo = (const float*)d_in[10];

    float* out  = (float*)d_out;                    // [B,S,H]
    float* attn = out + (long long)BB * SS * HH;    // [B,NH,S,S]

    float* Q;  cudaGetSymbolAddress((void**)&Q,  g_Q);
    float* Kb; cudaGetSymbolAddress((void**)&Kb, g_K);
    float* V;  cudaGetSymbolAddress((void**)&V,  g_V);
    float* Cx; cudaGetSymbolAddress((void**)&Cx, g_C);

    const int M = BB * SS;  // 8192

    // --- projections: Y = X @ W^T + b  (M=8192, N=512, K=512) ---
    {
        dim3 grid(HH / 128, M / 128, 1);
        dim3 blk(256);
        gemm_tc<128, 128, 32, 64, 32, true><<<grid, blk>>>(
            query, Wq, bq, Q, HH, HH, HH, HH, 0, 0, 0, 0, 0, 0, 1.0f);
        gemm_tc<128, 128, 32, 64, 32, true><<<grid, blk>>>(
            key_in, Wk, bk, Kb, HH, HH, HH, HH, 0, 0, 0, 0, 0, 0, 1.0f);
        gemm_tc<128, 128, 32, 64, 32, true><<<grid, blk>>>(
            value, Wv, bv, V, HH, HH, HH, HH, 0, 0, 0, 0, 0, 0, 1.0f);
    }

    // --- scores: attn = scale * Q @ K^T per (b,h) ---
    {
        dim3 grid(SS / 128, SS / 128, BB * NHH);
        dim3 blk(256);
        const long long sQb = (long long)SS * HH, sQh = HDD;
        const long long sCb = (long long)NHH * SS * SS, sCh = (long long)SS * SS;
        gemm_tc<128, 128, 32, 64, 32, true><<<grid, blk>>>(
            Q, Kb, nullptr, attn, HDD, HH, HH, SS,
            sQb, sQh, sQb, sQh, sCb, sCh, 0.125f);
    }

    // --- softmax rows ---
    softmax_kernel<<<BB * NHH * SS, 256>>>(attn);

    // --- context: Cx = attn @ V per (b,h)  (M=2048, N=64, K=2048) ---
    {
        dim3 grid(HDD / 64, SS / 128, BB * NHH);
        dim3 blk(256);
        const long long sAb = (long long)NHH * SS * SS, sAh = (long long)SS * SS;
        const long long sVb = (long long)SS * HH, sVh = HDD;
        gemm_tc<128, 64, 32, 32, 32, false><<<grid, blk>>>(
            attn, V, nullptr, Cx, SS, SS, HH, HH,
            sAb, sAh, sVb, sVh, sVb, sVh, 1.0f);
    }

    // --- output projection: out = Cx @ Wo^T + bo ---
    {
        dim3 grid(HH / 128, M / 128, 1);
        dim3 blk(256);
        gemm_tc<128, 128, 32, 64, 32, true><<<grid, blk>>>(
            Cx, Wo, bo, out, HH, HH, HH, HH, 0, 0, 0, 0, 0, 0, 1.0f);
    }
}

// round 3
// speedup vs baseline: 2.3926x; 1.2041x over previous
#include <cuda_runtime.h>
#include <cuda_bf16.h>

#define BB 4
#define SS 2048
#define HH 512
#define NHH 8
#define HDD 64

// Scratch (device globals: no allocation allowed in kernel_launch)
__device__ float g_Q[BB * SS * HH];
__device__ float g_K[BB * SS * HH];
__device__ float g_V[BB * SS * HH];
__device__ float g_C[BB * SS * HH];

__device__ __forceinline__ unsigned f2tf32(float x) {
    unsigned r;
    asm("cvt.rna.tf32.f32 %0, %1;" : "=r"(r) : "f"(x));
    return r;
}

__device__ __forceinline__ void mma_tf32(float* c,
                                         unsigned a0, unsigned a1, unsigned a2, unsigned a3,
                                         unsigned b0, unsigned b1) {
    asm volatile(
        "mma.sync.aligned.m16n8k8.row.col.f32.tf32.tf32.f32 "
        "{%0,%1,%2,%3}, {%4,%5,%6,%7}, {%8,%9}, {%0,%1,%2,%3};"
        : "+f"(c[0]), "+f"(c[1]), "+f"(c[2]), "+f"(c[3])
        : "r"(a0), "r"(a1), "r"(a2), "r"(a3), "r"(b0), "r"(b1));
}

__device__ __forceinline__ void cp16(unsigned dst, const void* src) {
    asm volatile("cp.async.cg.shared.global [%0], [%1], 16;" :: "r"(dst), "l"(src));
}
__device__ __forceinline__ void cp_commit() { asm volatile("cp.async.commit_group;"); }
__device__ __forceinline__ void cp_wait1() { asm volatile("cp.async.wait_group 1;"); }

// ---------------------------------------------------------------------------
// Tensor-core tf32 GEMM (projections / output projection).
//   C[m,n] = alpha * sum_k A[m*lda+k] * B[n*ldb+k] (+bias[n])
//   If ROUND: store result pre-rounded to tf32 bit pattern (for fused consumer).
// ---------------------------------------------------------------------------
template <int BM, int BN, int BK, int WM, int WN, bool ROUND>
__global__ __launch_bounds__((BM / WM) * (BN / WN) * 32)
void gemm_tc(const float* __restrict__ A,
             const float* __restrict__ Bm,
             const float* __restrict__ bias,
             float* __restrict__ C,
             int K, int lda, int ldb, int ldc, float alpha)
{
    constexpr int NWN = BN / WN;
    constexpr int THREADS = (BM / WM) * (BN / WN) * 32;
    constexpr int MT = WM / 16;
    constexpr int NT = WN / 8;
    constexpr int SA = BK + 4;
    constexpr int SB = BK + 4;

    __shared__ unsigned As[BM * SA];
    __shared__ unsigned Bs[BN * SB];

    const int bm = blockIdx.y * BM;
    const int bn = blockIdx.x * BN;
    const int tid = threadIdx.x;
    const int warpId = tid >> 5;
    const int lane = tid & 31;
    const int g = lane >> 2;
    const int tg = lane & 3;
    const int wm = warpId / NWN;
    const int wn = warpId % NWN;

    float c[MT][NT][4];
#pragma unroll
    for (int i = 0; i < MT; i++)
#pragma unroll
        for (int j = 0; j < NT; j++)
#pragma unroll
            for (int r = 0; r < 4; r++) c[i][j][r] = 0.0f;

    constexpr int A_ITERS = (BM * BK) / (THREADS * 4);
    constexpr int B_ITERS = (BN * BK) / (THREADS * 4);

    for (int k0 = 0; k0 < K; k0 += BK) {
#pragma unroll
        for (int it = 0; it < A_ITERS; it++) {
            int e = it * THREADS * 4 + tid * 4;
            int m = e / BK;
            int kk = e % BK;
            float4 v = *(const float4*)(A + (long long)(bm + m) * lda + k0 + kk);
            *(uint4*)&As[m * SA + kk] =
                make_uint4(f2tf32(v.x), f2tf32(v.y), f2tf32(v.z), f2tf32(v.w));
        }
#pragma unroll
        for (int it = 0; it < B_ITERS; it++) {
            int e = it * THREADS * 4 + tid * 4;
            int n = e / BK;
            int kk = e % BK;
            float4 v = *(const float4*)(Bm + (long long)(bn + n) * ldb + k0 + kk);
            *(uint4*)&Bs[n * SB + kk] =
                make_uint4(f2tf32(v.x), f2tf32(v.y), f2tf32(v.z), f2tf32(v.w));
        }
        __syncthreads();

#pragma unroll
        for (int kt = 0; kt < BK / 8; kt++) {
            unsigned a[MT][4], b[NT][2];
#pragma unroll
            for (int mt = 0; mt < MT; mt++) {
                int row = wm * WM + mt * 16 + g;
                int kb = kt * 8 + tg;
                a[mt][0] = As[row * SA + kb];
                a[mt][1] = As[(row + 8) * SA + kb];
                a[mt][2] = As[row * SA + kb + 4];
                a[mt][3] = As[(row + 8) * SA + kb + 4];
            }
#pragma unroll
            for (int nt = 0; nt < NT; nt++) {
                int col = wn * WN + nt * 8 + g;
                int kb = kt * 8 + tg;
                b[nt][0] = Bs[col * SB + kb];
                b[nt][1] = Bs[col * SB + kb + 4];
            }
#pragma unroll
            for (int mt = 0; mt < MT; mt++)
#pragma unroll
                for (int nt = 0; nt < NT; nt++)
                    mma_tf32(c[mt][nt], a[mt][0], a[mt][1], a[mt][2], a[mt][3],
                             b[nt][0], b[nt][1]);
        }
        __syncthreads();
    }

#pragma unroll
    for (int mt = 0; mt < MT; mt++) {
#pragma unroll
        for (int nt = 0; nt < NT; nt++) {
            int row = bm + wm * WM + mt * 16 + g;
            int col = bn + wn * WN + nt * 8 + 2 * tg;
            float bx = bias ? bias[col] : 0.0f;
            float by = bias ? bias[col + 1] : 0.0f;
            float ox0 = alpha * c[mt][nt][0] + bx;
            float oy0 = alpha * c[mt][nt][1] + by;
            float ox1 = alpha * c[mt][nt][2] + bx;
            float oy1 = alpha * c[mt][nt][3] + by;
            if (ROUND) {
                ox0 = __uint_as_float(f2tf32(ox0));
                oy0 = __uint_as_float(f2tf32(oy0));
                ox1 = __uint_as_float(f2tf32(ox1));
                oy1 = __uint_as_float(f2tf32(oy1));
            }
            *(float2*)(C + (long long)row * ldc + col) = make_float2(ox0, oy0);
            *(float2*)(C + (long long)(row + 8) * ldc + col) = make_float2(ox1, oy1);
        }
    }
}

// ---------------------------------------------------------------------------
// Fused attention: scores + softmax + context, one (b,h,qtile) per block.
// Two passes over K-tiles: pass1 computes row max & sum (scores recomputed in
// pass2). Q/K/V already hold tf32-rounded bit patterns.
// 8 warps; each warp owns 16 full Q-rows (WM=16, WN=128 -> NT=16).
// ---------------------------------------------------------------------------

// smem layout (in u32 words)
#define QS_OFF 0                 // 128*68
#define KS_OFF 8704              // 2 * 128*68
#define VS_OFF 26112             // 2 * 128*72
#define PS_OFF 44544             // 128*68
#define SMEM_WORDS 53248         // 212992 bytes

__global__ __launch_bounds__(256, 1)
void attn_fused(const float* __restrict__ Q,
                const float* __restrict__ K,
                const float* __restrict__ V,
                float* __restrict__ attn,
                float* __restrict__ Cx)
{
    extern __shared__ unsigned sm[];
    unsigned* Qs = sm + QS_OFF;
    unsigned* Ks = sm + KS_OFF;
    unsigned* Vs = sm + VS_OFF;
    unsigned* Ps = sm + PS_OFF;
    const unsigned sbase = (unsigned)__cvta_generic_to_shared(sm);

    const int tid = threadIdx.x;
    const int warpId = tid >> 5;
    const int lane = tid & 31;
    const int g = lane >> 2;
    const int tg = lane & 3;
    const int wrow = warpId * 16;

    const int qt = blockIdx.x;
    const int bh = blockIdx.y;
    const int b = bh >> 3;
    const int h = bh & 7;

    const float* Qg = Q + ((long long)b * SS + qt * 128) * HH + h * HDD;
    const float* Kg = K + (long long)b * SS * HH + h * HDD;
    const float* Vg = V + (long long)b * SS * HH + h * HDD;
    float* attng = attn + ((long long)bh * SS + qt * 128) * SS;
    float* Cg = Cx + ((long long)b * SS + qt * 128) * HH + h * HDD;

    // ---- tile loaders (cp.async, 16B granules, fully coalesced) ----
    auto loadK = [&](int t, int buf) {
        unsigned dstb = sbase + (KS_OFF + buf * 8704) * 4;
        const float* src = Kg + (long long)(t * 128) * HH;
#pragma unroll
        for (int i = 0; i < 8; i++) {
            int idx = tid + i * 256;
            int row = idx >> 4, cc = idx & 15;
            cp16(dstb + (row * 68 + cc * 4) * 4, src + (long long)row * HH + cc * 4);
        }
    };
    auto loadV = [&](int t, int buf) {
        unsigned dstb = sbase + (VS_OFF + buf * 9216) * 4;
        const float* src = Vg + (long long)(t * 128) * HH;
#pragma unroll
        for (int i = 0; i < 8; i++) {
            int idx = tid + i * 256;
            int row = idx >> 4, cc = idx & 15;
            cp16(dstb + (row * 72 + cc * 4) * 4, src + (long long)row * HH + cc * 4);
        }
    };

    // preload Q tile + K tile 0
    {
        unsigned dstb = sbase + QS_OFF * 4;
#pragma unroll
        for (int i = 0; i < 8; i++) {
            int idx = tid + i * 256;
            int row = idx >> 4, cc = idx & 15;
            cp16(dstb + (row * 68 + cc * 4) * 4, Qg + (long long)row * HH + cc * 4);
        }
        loadK(0, 0);
        cp_commit();
    }

    const float NEG_INF = __int_as_float(0xff800000);
    float m0 = NEG_INF, m1 = NEG_INF, l0 = 0.0f, l1 = 0.0f;
    float cf[16][4];

    // ---------------- pass 1: row max / sum ----------------
    for (int t = 0; t < 16; t++) {
        if (t < 15) loadK(t + 1, (t + 1) & 1);
        cp_commit();
        cp_wait1();
        __syncthreads();

        const unsigned* kb = Ks + (t & 1) * 8704;
#pragma unroll
        for (int nt = 0; nt < 16; nt++)
#pragma unroll
            for (int r = 0; r < 4; r++) cf[nt][r] = 0.0f;
#pragma unroll
        for (int kc = 0; kc < 8; kc++) {
            unsigned a0 = Qs[(wrow + g) * 68 + kc * 8 + tg];
            unsigned a1 = Qs[(wrow + g + 8) * 68 + kc * 8 + tg];
            unsigned a2 = Qs[(wrow + g) * 68 + kc * 8 + tg + 4];
            unsigned a3 = Qs[(wrow + g + 8) * 68 + kc * 8 + tg + 4];
#pragma unroll
            for (int nt = 0; nt < 16; nt++) {
                unsigned b0 = kb[(nt * 8 + g) * 68 + kc * 8 + tg];
                unsigned b1 = kb[(nt * 8 + g) * 68 + kc * 8 + tg + 4];
                mma_tf32(cf[nt], a0, a1, a2, a3, b0, b1);
            }
        }

        float tmax0 = NEG_INF, tmax1 = NEG_INF;
#pragma unroll
        for (int nt = 0; nt < 16; nt++) {
            tmax0 = fmaxf(tmax0, fmaxf(cf[nt][0], cf[nt][1]));
            tmax1 = fmaxf(tmax1, fmaxf(cf[nt][2], cf[nt][3]));
        }
        tmax0 = fmaxf(tmax0, __shfl_xor_sync(0xffffffffu, tmax0, 1));
        tmax0 = fmaxf(tmax0, __shfl_xor_sync(0xffffffffu, tmax0, 2));
        tmax1 = fmaxf(tmax1, __shfl_xor_sync(0xffffffffu, tmax1, 1));
        tmax1 = fmaxf(tmax1, __shfl_xor_sync(0xffffffffu, tmax1, 2));
        tmax0 *= 0.125f;
        tmax1 *= 0.125f;
        float mn0 = fmaxf(m0, tmax0);
        float mn1 = fmaxf(m1, tmax1);
        float s0 = 0.0f, s1 = 0.0f;
#pragma unroll
        for (int nt = 0; nt < 16; nt++) {
            s0 += __expf(0.125f * cf[nt][0] - mn0) + __expf(0.125f * cf[nt][1] - mn0);
            s1 += __expf(0.125f * cf[nt][2] - mn1) + __expf(0.125f * cf[nt][3] - mn1);
        }
        s0 += __shfl_xor_sync(0xffffffffu, s0, 1);
        s0 += __shfl_xor_sync(0xffffffffu, s0, 2);
        s1 += __shfl_xor_sync(0xffffffffu, s1, 1);
        s1 += __shfl_xor_sync(0xffffffffu, s1, 2);
        l0 = l0 * __expf(m0 - mn0) + s0;
        l1 = l1 * __expf(m1 - mn1) + s1;
        m0 = mn0;
        m1 = mn1;
        __syncthreads();
    }

    const float inv0 = 1.0f / l0;
    const float inv1 = 1.0f / l1;

    // ---------------- pass 2: normalized P -> gmem, O += P*V ----------------
    loadK(0, 0);
    loadV(0, 0);
    cp_commit();

    float of[8][4];
#pragma unroll
    for (int nt = 0; nt < 8; nt++)
#pragma unroll
        for (int r = 0; r < 4; r++) of[nt][r] = 0.0f;

    for (int t = 0; t < 16; t++) {
        if (t < 15) { loadK(t + 1, (t + 1) & 1); loadV(t + 1, (t + 1) & 1); }
        cp_commit();
        cp_wait1();
        __syncthreads();

        const unsigned* kb = Ks + (t & 1) * 8704;
        const unsigned* vb = Vs + (t & 1) * 9216;

#pragma unroll
        for (int nt = 0; nt < 16; nt++)
#pragma unroll
            for (int r = 0; r < 4; r++) cf[nt][r] = 0.0f;
#pragma unroll
        for (int kc = 0; kc < 8; kc++) {
            unsigned a0 = Qs[(wrow + g) * 68 + kc * 8 + tg];
            unsigned a1 = Qs[(wrow + g + 8) * 68 + kc * 8 + tg];
            unsigned a2 = Qs[(wrow + g) * 68 + kc * 8 + tg + 4];
            unsigned a3 = Qs[(wrow + g + 8) * 68 + kc * 8 + tg + 4];
#pragma unroll
            for (int nt = 0; nt < 16; nt++) {
                unsigned b0 = kb[(nt * 8 + g) * 68 + kc * 8 + tg];
                unsigned b1 = kb[(nt * 8 + g) * 68 + kc * 8 + tg + 4];
                mma_tf32(cf[nt], a0, a1, a2, a3, b0, b1);
            }
        }

        float* a0p = attng + (long long)(wrow + g) * SS + t * 128 + 2 * tg;
        float* a1p = attng + (long long)(wrow + g + 8) * SS + t * 128 + 2 * tg;

#pragma unroll
        for (int half = 0; half < 2; half++) {
#pragma unroll
            for (int j = 0; j < 8; j++) {
                int nt = half * 8 + j;
                float p0 = __expf(0.125f * cf[nt][0] - m0) * inv0;
                float p1 = __expf(0.125f * cf[nt][1] - m0) * inv0;
                float p2 = __expf(0.125f * cf[nt][2] - m1) * inv1;
                float p3 = __expf(0.125f * cf[nt][3] - m1) * inv1;
                asm volatile("st.global.cs.v2.f32 [%0], {%1,%2};"
                             :: "l"(a0p + nt * 8), "f"(p0), "f"(p1));
                asm volatile("st.global.cs.v2.f32 [%0], {%1,%2};"
                             :: "l"(a1p + nt * 8), "f"(p2), "f"(p3));
                Ps[(wrow + g) * 68 + j * 8 + 2 * tg] = f2tf32(p0);
                Ps[(wrow + g) * 68 + j * 8 + 2 * tg + 1] = f2tf32(p1);
                Ps[(wrow + g + 8) * 68 + j * 8 + 2 * tg] = f2tf32(p2);
                Ps[(wrow + g + 8) * 68 + j * 8 + 2 * tg + 1] = f2tf32(p3);
            }
            __syncwarp();
#pragma unroll
            for (int kc = 0; kc < 8; kc++) {
                unsigned a0 = Ps[(wrow + g) * 68 + kc * 8 + tg];
                unsigned a1 = Ps[(wrow + g + 8) * 68 + kc * 8 + tg];
                unsigned a2 = Ps[(wrow + g) * 68 + kc * 8 + tg + 4];
                unsigned a3 = Ps[(wrow + g + 8) * 68 + kc * 8 + tg + 4];
                int kr = half * 64 + kc * 8;
#pragma unroll
                for (int nt2 = 0; nt2 < 8; nt2++) {
                    unsigned b0 = vb[(kr + tg) * 72 + nt2 * 8 + g];
                    unsigned b1 = vb[(kr + tg + 4) * 72 + nt2 * 8 + g];
                    mma_tf32(of[nt2], a0, a1, a2, a3, b0, b1);
                }
            }
            __syncwarp();
        }
        __syncthreads();
    }

    // ---- O epilogue ----
#pragma unroll
    for (int nt2 = 0; nt2 < 8; nt2++) {
        int col = nt2 * 8 + 2 * tg;
        *(float2*)(Cg + (long long)(wrow + g) * HH + col) =
            make_float2(of[nt2][0], of[nt2][1]);
        *(float2*)(Cg + (long long)(wrow + g + 8) * HH + col) =
            make_float2(of[nt2][2], of[nt2][3]);
    }
}

// ---------------------------------------------------------------------------
extern "C" void kernel_launch(void* const* d_in, const int* in_sizes, int n_in,
                              void* d_out, int out_size)
{
    const float* query  = (const float*)d_in[0];
    const float* key_in = (const float*)d_in[1];
    const float* value  = (const float*)d_in[2];
    const float* Wq = (const float*)d_in[3];
    const float* bq = (const float*)d_in[4];
    const float* Wk = (const float*)d_in[5];
    const float* bk = (const float*)d_in[6];
    const float* Wv = (const float*)d_in[7];
    const float* bv = (const float*)d_in[8];
    const float* Wo = (const float*)d_in[9];
    const float* bo = (const float*)d_in[10];

    float* out  = (float*)d_out;                    // [B,S,H]
    float* attn = out + (long long)BB * SS * HH;    // [B,NH,S,S]

    float* Q;  cudaGetSymbolAddress((void**)&Q,  g_Q);
    float* Kb; cudaGetSymbolAddress((void**)&Kb, g_K);
    float* V;  cudaGetSymbolAddress((void**)&V,  g_V);
    float* Cx; cudaGetSymbolAddress((void**)&Cx, g_C);

    cudaFuncSetAttribute(attn_fused,
                         cudaFuncAttributeMaxDynamicSharedMemorySize,
                         SMEM_WORDS * 4);

    const int M = BB * SS;  // 8192

    // --- projections (outputs pre-rounded to tf32 bits) ---
    {
        dim3 grid(HH / 128, M / 128);
        dim3 blk(256);
        gemm_tc<128, 128, 32, 64, 32, true><<<grid, blk>>>(
            query, Wq, bq, Q, HH, HH, HH, HH, 1.0f);
        gemm_tc<128, 128, 32, 64, 32, true><<<grid, blk>>>(
            key_in, Wk, bk, Kb, HH, HH, HH, HH, 1.0f);
        gemm_tc<128, 128, 32, 64, 32, true><<<grid, blk>>>(
            value, Wv, bv, V, HH, HH, HH, HH, 1.0f);
    }

    // --- fused scores + softmax + context ---
    {
        dim3 grid(SS / 128, BB * NHH);   // (qtile, b*NH+h)
        attn_fused<<<grid, 256, SMEM_WORDS * 4>>>(Q, Kb, V, attn, Cx);
    }

    // --- output projection: out = Cx @ Wo^T + bo ---
    {
        dim3 grid(HH / 128, M / 128);
        dim3 blk(256);
        gemm_tc<128, 128, 32, 64, 32, false><<<grid, blk>>>(
            Cx, Wo, bo, out, HH, HH, HH, HH, 1.0f);
    }
}

// round 4
// speedup vs baseline: 2.5822x; 1.0792x over previous
#include <cuda_runtime.h>
#include <cuda_bf16.h>

#define BB 4
#define SS 2048
#define HH 512
#define NHH 8
#define HDD 64

// Scratch (device globals: no allocation allowed in kernel_launch)
__device__ float g_Q[BB * SS * HH];
__device__ float g_K[BB * SS * HH];
__device__ float g_V[BB * SS * HH];
__device__ float g_C[BB * SS * HH];

__device__ __forceinline__ unsigned f2tf32(float x) {
    unsigned r;
    asm("cvt.rna.tf32.f32 %0, %1;" : "=r"(r) : "f"(x));
    return r;
}

__device__ __forceinline__ void mma_tf32(float* c,
                                         unsigned a0, unsigned a1, unsigned a2, unsigned a3,
                                         unsigned b0, unsigned b1) {
    asm volatile(
        "mma.sync.aligned.m16n8k8.row.col.f32.tf32.tf32.f32 "
        "{%0,%1,%2,%3}, {%4,%5,%6,%7}, {%8,%9}, {%0,%1,%2,%3};"
        : "+f"(c[0]), "+f"(c[1]), "+f"(c[2]), "+f"(c[3])
        : "r"(a0), "r"(a1), "r"(a2), "r"(a3), "r"(b0), "r"(b1));
}

__device__ __forceinline__ void cp16(unsigned dst, const void* src) {
    asm volatile("cp.async.cg.shared.global [%0], [%1], 16;" :: "r"(dst), "l"(src));
}
__device__ __forceinline__ void cp_commit() { asm volatile("cp.async.commit_group;"); }
__device__ __forceinline__ void cp_wait1() { asm volatile("cp.async.wait_group 1;"); }

// ---------------------------------------------------------------------------
// Tensor-core tf32 GEMM (projections / output projection).
//   C[m,n] = alpha * sum_k A[m*lda+k] * B[n*ldb+k] (+bias[n])
//   If ROUND: store result pre-rounded to tf32 bit pattern (for fused consumer).
// ---------------------------------------------------------------------------
template <int BM, int BN, int BK, int WM, int WN, bool ROUND>
__global__ __launch_bounds__((BM / WM) * (BN / WN) * 32)
void gemm_tc(const float* __restrict__ A,
             const float* __restrict__ Bm,
             const float* __restrict__ bias,
             float* __restrict__ C,
             int K, int lda, int ldb, int ldc, float alpha)
{
    constexpr int NWN = BN / WN;
    constexpr int THREADS = (BM / WM) * (BN / WN) * 32;
    constexpr int MT = WM / 16;
    constexpr int NT = WN / 8;
    constexpr int SA = BK + 4;
    constexpr int SB = BK + 4;

    __shared__ unsigned As[BM * SA];
    __shared__ unsigned Bs[BN * SB];

    const int bm = blockIdx.y * BM;
    const int bn = blockIdx.x * BN;
    const int tid = threadIdx.x;
    const int warpId = tid >> 5;
    const int lane = tid & 31;
    const int g = lane >> 2;
    const int tg = lane & 3;
    const int wm = warpId / NWN;
    const int wn = warpId % NWN;

    float c[MT][NT][4];
#pragma unroll
    for (int i = 0; i < MT; i++)
#pragma unroll
        for (int j = 0; j < NT; j++)
#pragma unroll
            for (int r = 0; r < 4; r++) c[i][j][r] = 0.0f;

    constexpr int A_ITERS = (BM * BK) / (THREADS * 4);
    constexpr int B_ITERS = (BN * BK) / (THREADS * 4);

    for (int k0 = 0; k0 < K; k0 += BK) {
#pragma unroll
        for (int it = 0; it < A_ITERS; it++) {
            int e = it * THREADS * 4 + tid * 4;
            int m = e / BK;
            int kk = e % BK;
            float4 v = *(const float4*)(A + (long long)(bm + m) * lda + k0 + kk);
            *(uint4*)&As[m * SA + kk] =
                make_uint4(f2tf32(v.x), f2tf32(v.y), f2tf32(v.z), f2tf32(v.w));
        }
#pragma unroll
        for (int it = 0; it < B_ITERS; it++) {
            int e = it * THREADS * 4 + tid * 4;
            int n = e / BK;
            int kk = e % BK;
            float4 v = *(const float4*)(Bm + (long long)(bn + n) * ldb + k0 + kk);
            *(uint4*)&Bs[n * SB + kk] =
                make_uint4(f2tf32(v.x), f2tf32(v.y), f2tf32(v.z), f2tf32(v.w));
        }
        __syncthreads();

#pragma unroll
        for (int kt = 0; kt < BK / 8; kt++) {
            unsigned a[MT][4], b[NT][2];
#pragma unroll
            for (int mt = 0; mt < MT; mt++) {
                int row = wm * WM + mt * 16 + g;
                int kb = kt * 8 + tg;
                a[mt][0] = As[row * SA + kb];
                a[mt][1] = As[(row + 8) * SA + kb];
                a[mt][2] = As[row * SA + kb + 4];
                a[mt][3] = As[(row + 8) * SA + kb + 4];
            }
#pragma unroll
            for (int nt = 0; nt < NT; nt++) {
                int col = wn * WN + nt * 8 + g;
                int kb = kt * 8 + tg;
                b[nt][0] = Bs[col * SB + kb];
                b[nt][1] = Bs[col * SB + kb + 4];
            }
#pragma unroll
            for (int mt = 0; mt < MT; mt++)
#pragma unroll
                for (int nt = 0; nt < NT; nt++)
                    mma_tf32(c[mt][nt], a[mt][0], a[mt][1], a[mt][2], a[mt][3],
                             b[nt][0], b[nt][1]);
        }
        __syncthreads();
    }

#pragma unroll
    for (int mt = 0; mt < MT; mt++) {
#pragma unroll
        for (int nt = 0; nt < NT; nt++) {
            int row = bm + wm * WM + mt * 16 + g;
            int col = bn + wn * WN + nt * 8 + 2 * tg;
            float bx = bias ? bias[col] : 0.0f;
            float by = bias ? bias[col + 1] : 0.0f;
            float ox0 = alpha * c[mt][nt][0] + bx;
            float oy0 = alpha * c[mt][nt][1] + by;
            float ox1 = alpha * c[mt][nt][2] + bx;
            float oy1 = alpha * c[mt][nt][3] + by;
            if (ROUND) {
                ox0 = __uint_as_float(f2tf32(ox0));
                oy0 = __uint_as_float(f2tf32(oy0));
                ox1 = __uint_as_float(f2tf32(ox1));
                oy1 = __uint_as_float(f2tf32(oy1));
            }
            *(float2*)(C + (long long)row * ldc + col) = make_float2(ox0, oy0);
            *(float2*)(C + (long long)(row + 8) * ldc + col) = make_float2(ox1, oy1);
        }
    }
}

// ---------------------------------------------------------------------------
// Fused attention: scores + softmax + context.
// 512 threads = 16 warps; Q tile = 256 rows (16 per warp); K/V tiles = 64 rows,
// double buffered. No max subtraction (scores bounded); two passes:
//   pass1: l[row] = sum exp2(s * log2e/8)       (per-thread, reduced once)
//   pass2: p = 2^(s*C + log2(1/l)) -> attn (gmem) and P·V via register permute.
// ---------------------------------------------------------------------------

// smem layout (u32 words)
#define QS_OFF 0                 // 256*68 = 17408
#define KS_OFF 17408             // 2 * 64*68 = 8704
#define VS_OFF 26112             // 2 * 64*72 = 9216
#define SMEM_WORDS 35328         // 141312 bytes

#define EXPC 0.18033688011112042f   // log2(e)/8

__global__ __launch_bounds__(512, 1)
void attn_fused(const float* __restrict__ Q,
                const float* __restrict__ K,
                const float* __restrict__ V,
                float* __restrict__ attn,
                float* __restrict__ Cx)
{
    extern __shared__ unsigned sm[];
    unsigned* Qs = sm + QS_OFF;
    unsigned* Ks = sm + KS_OFF;
    unsigned* Vs = sm + VS_OFF;
    const unsigned sbase = (unsigned)__cvta_generic_to_shared(sm);

    const int tid = threadIdx.x;
    const int warpId = tid >> 5;
    const int lane = tid & 31;
    const int g = lane >> 2;
    const int tg = lane & 3;
    const int wrow = warpId * 16;

    const int qt = blockIdx.x;           // 0..7 (256-row q tiles)
    const int bh = blockIdx.y;           // 0..31
    const int b = bh >> 3;
    const int h = bh & 7;

    const float* Qg = Q + ((long long)b * SS + qt * 256) * HH + h * HDD;
    const float* Kg = K + (long long)b * SS * HH + h * HDD;
    const float* Vg = V + (long long)b * SS * HH + h * HDD;
    float* attng = attn + ((long long)bh * SS + qt * 256 + wrow) * SS;
    float* Cg = Cx + ((long long)b * SS + qt * 256 + wrow) * HH + h * HDD;

    // ---- tile loaders: 64-row K/V tiles, 16B granules ----
    auto loadK = [&](int t, int buf) {
        unsigned dstb = sbase + (KS_OFF + buf * 4352) * 4;
        const float* src = Kg + (long long)(t * 64) * HH;
#pragma unroll
        for (int i = 0; i < 2; i++) {
            int idx = tid + i * 512;
            int row = idx >> 4, cc = idx & 15;
            cp16(dstb + (row * 68 + cc * 4) * 4, src + (long long)row * HH + cc * 4);
        }
    };
    auto loadV = [&](int t, int buf) {
        unsigned dstb = sbase + (VS_OFF + buf * 4608) * 4;
        const float* src = Vg + (long long)(t * 64) * HH;
#pragma unroll
        for (int i = 0; i < 2; i++) {
            int idx = tid + i * 512;
            int row = idx >> 4, cc = idx & 15;
            cp16(dstb + (row * 72 + cc * 4) * 4, src + (long long)row * HH + cc * 4);
        }
    };

    // preload Q tile (256 rows) + K tile 0
    {
        unsigned dstb = sbase + QS_OFF * 4;
#pragma unroll
        for (int i = 0; i < 8; i++) {
            int idx = tid + i * 512;
            int row = idx >> 4, cc = idx & 15;
            cp16(dstb + (row * 68 + cc * 4) * 4, Qg + (long long)row * HH + cc * 4);
        }
        loadK(0, 0);
        cp_commit();
    }

    float l0 = 0.0f, l1 = 0.0f;
    float cf[8][4];

    // ---------------- pass 1: row sums of exp ----------------
    for (int t = 0; t < 32; t++) {
        if (t < 31) loadK(t + 1, (t + 1) & 1);
        cp_commit();
        cp_wait1();
        __syncthreads();

        const unsigned* kb = Ks + (t & 1) * 4352;
#pragma unroll
        for (int nt = 0; nt < 8; nt++)
#pragma unroll
            for (int r = 0; r < 4; r++) cf[nt][r] = 0.0f;
#pragma unroll
        for (int kc = 0; kc < 8; kc++) {
            unsigned a0 = Qs[(wrow + g) * 68 + kc * 8 + tg];
            unsigned a1 = Qs[(wrow + g + 8) * 68 + kc * 8 + tg];
            unsigned a2 = Qs[(wrow + g) * 68 + kc * 8 + tg + 4];
            unsigned a3 = Qs[(wrow + g + 8) * 68 + kc * 8 + tg + 4];
#pragma unroll
            for (int nt = 0; nt < 8; nt++) {
                unsigned b0 = kb[(nt * 8 + g) * 68 + kc * 8 + tg];
                unsigned b1 = kb[(nt * 8 + g) * 68 + kc * 8 + tg + 4];
                mma_tf32(cf[nt], a0, a1, a2, a3, b0, b1);
            }
        }
#pragma unroll
        for (int nt = 0; nt < 8; nt++) {
            l0 += exp2f(cf[nt][0] * EXPC) + exp2f(cf[nt][1] * EXPC);
            l1 += exp2f(cf[nt][2] * EXPC) + exp2f(cf[nt][3] * EXPC);
        }
        __syncthreads();
    }

    // quad reduce (threads tg=0..3 share a row)
    l0 += __shfl_xor_sync(0xffffffffu, l0, 1);
    l0 += __shfl_xor_sync(0xffffffffu, l0, 2);
    l1 += __shfl_xor_sync(0xffffffffu, l1, 1);
    l1 += __shfl_xor_sync(0xffffffffu, l1, 2);
    const float li0 = -__log2f(l0);
    const float li1 = -__log2f(l1);

    // ---------------- pass 2: normalized P -> gmem, O += P*V ----------------
    loadK(0, 0);
    loadV(0, 0);
    cp_commit();

    float of[8][4];
#pragma unroll
    for (int nt = 0; nt < 8; nt++)
#pragma unroll
        for (int r = 0; r < 4; r++) of[nt][r] = 0.0f;

    const int src1 = (lane & ~3) | (tg >> 1);
    const int src2 = src1 + 2;
    const bool odd = (tg & 1) != 0;

    for (int t = 0; t < 32; t++) {
        if (t < 31) { loadK(t + 1, (t + 1) & 1); loadV(t + 1, (t + 1) & 1); }
        cp_commit();
        cp_wait1();
        __syncthreads();

        const unsigned* kb = Ks + (t & 1) * 4352;
        const unsigned* vb = Vs + (t & 1) * 4608;

#pragma unroll
        for (int nt = 0; nt < 8; nt++)
#pragma unroll
            for (int r = 0; r < 4; r++) cf[nt][r] = 0.0f;
#pragma unroll
        for (int kc = 0; kc < 8; kc++) {
            unsigned a0 = Qs[(wrow + g) * 68 + kc * 8 + tg];
            unsigned a1 = Qs[(wrow + g + 8) * 68 + kc * 8 + tg];
            unsigned a2 = Qs[(wrow + g) * 68 + kc * 8 + tg + 4];
            unsigned a3 = Qs[(wrow + g + 8) * 68 + kc * 8 + tg + 4];
#pragma unroll
            for (int nt = 0; nt < 8; nt++) {
                unsigned b0 = kb[(nt * 8 + g) * 68 + kc * 8 + tg];
                unsigned b1 = kb[(nt * 8 + g) * 68 + kc * 8 + tg + 4];
                mma_tf32(cf[nt], a0, a1, a2, a3, b0, b1);
            }
        }

#pragma unroll
        for (int c = 0; c < 8; c++) {
            float p0 = exp2f(fmaf(cf[c][0], EXPC, li0));
            float p1 = exp2f(fmaf(cf[c][1], EXPC, li0));
            float p2 = exp2f(fmaf(cf[c][2], EXPC, li1));
            float p3 = exp2f(fmaf(cf[c][3], EXPC, li1));

            // attn gmem (streaming stores, 32B-sector aligned per quad)
            float* ap0 = attng + (long long)g * SS + t * 64 + c * 8 + 2 * tg;
            float* ap1 = ap0 + 8LL * SS;
            asm volatile("st.global.cs.v2.f32 [%0], {%1,%2};" :: "l"(ap0), "f"(p0), "f"(p1));
            asm volatile("st.global.cs.v2.f32 [%0], {%1,%2};" :: "l"(ap1), "f"(p2), "f"(p3));

            // register permute: C-fragment -> A-fragment (quad shuffle)
            unsigned e0 = f2tf32(p0), e1 = f2tf32(p1), e2 = f2tf32(p2), e3 = f2tf32(p3);
            unsigned x0 = __shfl_sync(0xffffffffu, e0, src1);
            unsigned x1 = __shfl_sync(0xffffffffu, e1, src1);
            unsigned x2 = __shfl_sync(0xffffffffu, e2, src1);
            unsigned x3 = __shfl_sync(0xffffffffu, e3, src1);
            unsigned y0 = __shfl_sync(0xffffffffu, e0, src2);
            unsigned y1 = __shfl_sync(0xffffffffu, e1, src2);
            unsigned y2 = __shfl_sync(0xffffffffu, e2, src2);
            unsigned y3 = __shfl_sync(0xffffffffu, e3, src2);
            unsigned a0 = odd ? x1 : x0;
            unsigned a1 = odd ? x3 : x2;
            unsigned a2 = odd ? y1 : y0;
            unsigned a3 = odd ? y3 : y2;

#pragma unroll
            for (int nt2 = 0; nt2 < 8; nt2++) {
                unsigned b0 = vb[(c * 8 + tg) * 72 + nt2 * 8 + g];
                unsigned b1 = vb[(c * 8 + tg + 4) * 72 + nt2 * 8 + g];
                mma_tf32(of[nt2], a0, a1, a2, a3, b0, b1);
            }
        }
        __syncthreads();
    }

    // ---- O epilogue ----
#pragma unroll
    for (int nt2 = 0; nt2 < 8; nt2++) {
        int col = nt2 * 8 + 2 * tg;
        *(float2*)(Cg + (long long)g * HH + col) = make_float2(of[nt2][0], of[nt2][1]);
        *(float2*)(Cg + (long long)(g + 8) * HH + col) = make_float2(of[nt2][2], of[nt2][3]);
    }
}

// ---------------------------------------------------------------------------
extern "C" void kernel_launch(void* const* d_in, const int* in_sizes, int n_in,
                              void* d_out, int out_size)
{
    const float* query  = (const float*)d_in[0];
    const float* key_in = (const float*)d_in[1];
    const float* value  = (const float*)d_in[2];
    const float* Wq = (const float*)d_in[3];
    const float* bq = (const float*)d_in[4];
    const float* Wk = (const float*)d_in[5];
    const float* bk = (const float*)d_in[6];
    const float* Wv = (const float*)d_in[7];
    const float* bv = (const float*)d_in[8];
    const float* Wo = (const float*)d_in[9];
    const float* bo = (const float*)d_in[10];

    float* out  = (float*)d_out;                    // [B,S,H]
    float* attn = out + (long long)BB * SS * HH;    // [B,NH,S,S]

    float* Q;  cudaGetSymbolAddress((void**)&Q,  g_Q);
    float* Kb; cudaGetSymbolAddress((void**)&Kb, g_K);
    float* V;  cudaGetSymbolAddress((void**)&V,  g_V);
    float* Cx; cudaGetSymbolAddress((void**)&Cx, g_C);

    cudaFuncSetAttribute(attn_fused,
                         cudaFuncAttributeMaxDynamicSharedMemorySize,
                         SMEM_WORDS * 4);

    const int M = BB * SS;  // 8192

    // --- projections (outputs pre-rounded to tf32 bits) ---
    {
        dim3 grid(HH / 128, M / 128);
        dim3 blk(256);
        gemm_tc<128, 128, 32, 64, 32, true><<<grid, blk>>>(
            query, Wq, bq, Q, HH, HH, HH, HH, 1.0f);
        gemm_tc<128, 128, 32, 64, 32, true><<<grid, blk>>>(
            key_in, Wk, bk, Kb, HH, HH, HH, HH, 1.0f);
        gemm_tc<128, 128, 32, 64, 32, true><<<grid, blk>>>(
            value, Wv, bv, V, HH, HH, HH, HH, 1.0f);
    }

    // --- fused scores + softmax + context ---
    {
        dim3 grid(SS / 256, BB * NHH);   // (qtile, b*NH+h)
        attn_fused<<<grid, 512, SMEM_WORDS * 4>>>(Q, Kb, V, attn, Cx);
    }

    // --- output projection: out = Cx @ Wo^T + bo ---
    {
        dim3 grid(HH / 128, M / 128);
        dim3 blk(256);
        gemm_tc<128, 128, 32, 64, 32, false><<<grid, blk>>>(
            Cx, Wo, bo, out, HH, HH, HH, HH, 1.0f);
    }
}

// round 6
// speedup vs baseline: 4.2835x; 1.6589x over previous
#include <cuda_runtime.h>
#include <cuda_fp16.h>
#include <cstdint>

#define BB 4
#define SS 2048
#define HH 512
#define NHH 8
#define HDD 64
#define EXPC 0.18033688011112042f   // log2(e)/8

// Scratch (device globals: no allocation allowed in kernel_launch)
__device__ __half g_Qh[BB * SS * HH];
__device__ __half g_Kh[BB * SS * HH];
__device__ __half g_Vh[BB * SS * HH];   // V^T: [b][h][d][s]
__device__ __half g_Ch[BB * SS * HH];   // context, [b*s][h]

__device__ __forceinline__ float ex2(float x) {
    float y; asm("ex2.approx.ftz.f32 %0, %1;" : "=f"(y) : "f"(x)); return y;
}
__device__ __forceinline__ void cp16(unsigned dst, const void* src) {
    asm volatile("cp.async.cg.shared.global [%0], [%1], 16;" :: "r"(dst), "l"(src));
}
__device__ __forceinline__ void cp_commit() { asm volatile("cp.async.commit_group;"); }
__device__ __forceinline__ void cp_wait1() { asm volatile("cp.async.wait_group 1;"); }
__device__ __forceinline__ void cp_wait0() { asm volatile("cp.async.wait_group 0;"); }

__device__ __forceinline__ void mma_f16(float* c, const unsigned* a, const unsigned* b) {
    asm volatile(
        "mma.sync.aligned.m16n8k16.row.col.f32.f16.f16.f32 "
        "{%0,%1,%2,%3}, {%4,%5,%6,%7}, {%8,%9}, {%0,%1,%2,%3};"
        : "+f"(c[0]), "+f"(c[1]), "+f"(c[2]), "+f"(c[3])
        : "r"(a[0]), "r"(a[1]), "r"(a[2]), "r"(a[3]), "r"(b[0]), "r"(b[1]));
}
__device__ __forceinline__ unsigned packh2(float lo, float hi) {
    __half2 h = __floats2half2_rn(lo, hi);
    return *(unsigned*)&h;
}

// ---------------------------------------------------------------------------
// fp16 tensor-core GEMM: C[m,n] = sum_k A[m,k]*W[n,k] + bias[n]
// M=8192, N=512, K=512 fixed. BM=BN=128, BK=32. 8 warps: WM64 x WN32.
// INMODE: 0 = A fp32 (convert on stage), 1 = A fp16 (direct stage)
// OUTMODE: 0 = fp32 row-major, 1 = fp16 row-major, 2 = fp16 transposed V^T
// ---------------------------------------------------------------------------
template <int INMODE, int OUTMODE>
__global__ __launch_bounds__(256, 2)
void gemm_f16(const void* __restrict__ Ain, const float* __restrict__ W,
              const float* __restrict__ bias, void* __restrict__ Cout)
{
    __shared__ __align__(16) __half As[128][40];
    __shared__ __align__(16) __half Bs[128][40];
    const unsigned* Asw = (const unsigned*)&As[0][0];
    const unsigned* Bsw = (const unsigned*)&Bs[0][0];

    const int bm = blockIdx.y * 128;
    const int bn = blockIdx.x * 128;
    const int tid = threadIdx.x;
    const int warpId = tid >> 5, lane = tid & 31;
    const int g = lane >> 2, tg = lane & 3;
    const int wm = warpId >> 2;   // 0..1
    const int wn = warpId & 3;    // 0..3

    float c[4][4][4];
#pragma unroll
    for (int i = 0; i < 4; i++)
#pragma unroll
        for (int j = 0; j < 4; j++)
#pragma unroll
            for (int r = 0; r < 4; r++) c[i][j][r] = 0.0f;

    for (int k0 = 0; k0 < 512; k0 += 32) {
        if (INMODE == 0) {
            const float* A = (const float*)Ain;
#pragma unroll
            for (int it = 0; it < 4; it++) {
                int e = (tid + it * 256) * 4;
                int m = e >> 5, kk = e & 31;
                float4 v = *(const float4*)(A + (long long)(bm + m) * 512 + k0 + kk);
                *(__half2*)&As[m][kk]     = __floats2half2_rn(v.x, v.y);
                *(__half2*)&As[m][kk + 2] = __floats2half2_rn(v.z, v.w);
            }
        } else {
            const __half* A = (const __half*)Ain;
#pragma unroll
            for (int it = 0; it < 2; it++) {
                int e = (tid + it * 256) * 8;
                int m = e >> 5, kk = e & 31;
                *(uint4*)&As[m][kk] = *(const uint4*)(A + (long long)(bm + m) * 512 + k0 + kk);
            }
        }
#pragma unroll
        for (int it = 0; it < 4; it++) {
            int e = (tid + it * 256) * 4;
            int n = e >> 5, kk = e & 31;
            float4 v = *(const float4*)(W + (long long)(bn + n) * 512 + k0 + kk);
            *(__half2*)&Bs[n][kk]     = __floats2half2_rn(v.x, v.y);
            *(__half2*)&Bs[n][kk + 2] = __floats2half2_rn(v.z, v.w);
        }
        __syncthreads();

#pragma unroll
        for (int kc = 0; kc < 2; kc++) {
            unsigned a[4][4], b[4][2];
#pragma unroll
            for (int mt = 0; mt < 4; mt++) {
                int row = wm * 64 + mt * 16 + g;
                a[mt][0] = Asw[row * 20 + kc * 8 + tg];
                a[mt][1] = Asw[(row + 8) * 20 + kc * 8 + tg];
                a[mt][2] = Asw[row * 20 + kc * 8 + tg + 4];
                a[mt][3] = Asw[(row + 8) * 20 + kc * 8 + tg + 4];
            }
#pragma unroll
            for (int nt = 0; nt < 4; nt++) {
                int col = wn * 32 + nt * 8 + g;
                b[nt][0] = Bsw[col * 20 + kc * 8 + tg];
                b[nt][1] = Bsw[col * 20 + kc * 8 + tg + 4];
            }
#pragma unroll
            for (int mt = 0; mt < 4; mt++)
#pragma unroll
                for (int nt = 0; nt < 4; nt++)
                    mma_f16(c[mt][nt], a[mt], b[nt]);
        }
        __syncthreads();
    }

#pragma unroll
    for (int mt = 0; mt < 4; mt++) {
#pragma unroll
        for (int nt = 0; nt < 4; nt++) {
            int row = bm + wm * 64 + mt * 16 + g;
            int col = bn + wn * 32 + nt * 8 + 2 * tg;
            float bx = bias[col], by = bias[col + 1];
            float o0 = c[mt][nt][0] + bx, o1 = c[mt][nt][1] + by;
            float o2 = c[mt][nt][2] + bx, o3 = c[mt][nt][3] + by;
            if (OUTMODE == 0) {
                float* Cf = (float*)Cout;
                *(float2*)(Cf + (long long)row * 512 + col) = make_float2(o0, o1);
                *(float2*)(Cf + (long long)(row + 8) * 512 + col) = make_float2(o2, o3);
            } else if (OUTMODE == 1) {
                __half* Ch = (__half*)Cout;
                *(__half2*)(Ch + (long long)row * 512 + col) = __floats2half2_rn(o0, o1);
                *(__half2*)(Ch + (long long)(row + 8) * 512 + col) = __floats2half2_rn(o2, o3);
            } else {
                // V^T: [b][h][d][s]
                __half* Ch = (__half*)Cout;
                int bo = row >> 11, so = row & 2047;
                int ho = col >> 6, dd = col & 63;
                long long base = (((long long)bo * NHH + ho) * HDD + dd) * SS + so;
                Ch[base]           = __float2half_rn(o0);
                Ch[base + SS]      = __float2half_rn(o1);
                Ch[base + 8]       = __float2half_rn(o2);
                Ch[base + SS + 8]  = __float2half_rn(o3);
            }
        }
    }
}

// ---------------------------------------------------------------------------
// Fused attention, fp16 operands / fp32 accum.
// 256 threads (8 warps), Q tile = 128 rows (16/warp, WM16 x WN64), K/V tiles
// 64 rows double-buffered, grid (16, 32) = 512 CTAs, 2 CTAs/SM.
// Pass1: l = sum exp2(s*EXPC); Pass2: p = 2^(s*EXPC - log2 l) -> attn + P*V
// (P fed to PV mma directly from registers: fp16 C-frag == A-frag layout).
// ---------------------------------------------------------------------------
#define KOFF 18432
#define VOFF 36864
#define FUSED_SMEM 55296

__global__ __launch_bounds__(256, 2)
void attn_fused(const __half* __restrict__ Q,
                const __half* __restrict__ K,
                const __half* __restrict__ V,
                float* __restrict__ attn,
                __half* __restrict__ Cx)
{
    extern __shared__ __align__(16) unsigned char smraw[];
    const unsigned sb = (unsigned)__cvta_generic_to_shared(smraw);
    const unsigned* smw = (const unsigned*)smraw;

    const int tid = threadIdx.x;
    const int wid = tid >> 5;
    const int lane = tid & 31;
    const int g = lane >> 2, tg = lane & 3;
    const int wrow = wid * 16;

    const int qt = blockIdx.x;     // 0..15
    const int bh = blockIdx.y;     // 0..31
    const int b = bh >> 3, h = bh & 7;

    const __half* Qg = Q + ((long long)b * SS + qt * 128) * HH + h * HDD;
    const __half* Kg = K + (long long)b * SS * HH + h * HDD;
    const __half* Vg = V + (long long)bh * HDD * SS;

    auto stageK = [&](int t, int buf) {
#pragma unroll
        for (int i = 0; i < 2; i++) {
            int idx = tid + i * 256;
            int row = idx >> 3, cc = idx & 7;
            cp16(sb + KOFF + buf * 9216 + row * 144 + cc * 16,
                 Kg + (long long)(t * 64 + row) * HH + cc * 8);
        }
    };
    auto stageV = [&](int t, int buf) {
#pragma unroll
        for (int i = 0; i < 2; i++) {
            int idx = tid + i * 256;
            int row = idx >> 3, cc = idx & 7;    // row = d
            cp16(sb + VOFF + buf * 9216 + row * 144 + cc * 16,
                 Vg + (long long)row * SS + t * 64 + cc * 8);
        }
    };

    // stage Q (128 rows) + K tile 0
#pragma unroll
    for (int i = 0; i < 4; i++) {
        int idx = tid + i * 256;
        int row = idx >> 3, cc = idx & 7;
        cp16(sb + row * 144 + cc * 16, Qg + (long long)row * HH + cc * 8);
    }
    stageK(0, 0);
    cp_commit();
    cp_wait0();
    __syncthreads();

    // persistent Q A-fragments (k-invariant): 16 regs
    unsigned aq[4][4];
#pragma unroll
    for (int kc = 0; kc < 4; kc++) {
        aq[kc][0] = smw[(wrow + g) * 36 + kc * 8 + tg];
        aq[kc][1] = smw[(wrow + g + 8) * 36 + kc * 8 + tg];
        aq[kc][2] = smw[(wrow + g) * 36 + kc * 8 + tg + 4];
        aq[kc][3] = smw[(wrow + g + 8) * 36 + kc * 8 + tg + 4];
    }

    float l0 = 0.0f, l1 = 0.0f;
    float s[8][4];

    // ================= pass 1: row sums =================
    for (int t = 0; t < 32; t++) {
        if (t < 31) stageK(t + 1, (t + 1) & 1);
        cp_commit();
        cp_wait1();
        __syncthreads();

        const unsigned* kb = smw + 4608 + (t & 1) * 2304;
#pragma unroll
        for (int nt = 0; nt < 8; nt++)
#pragma unroll
            for (int r = 0; r < 4; r++) s[nt][r] = 0.0f;
#pragma unroll
        for (int kc = 0; kc < 4; kc++) {
#pragma unroll
            for (int nt = 0; nt < 8; nt++) {
                unsigned bfr[2];
                bfr[0] = kb[(nt * 8 + g) * 36 + kc * 8 + tg];
                bfr[1] = kb[(nt * 8 + g) * 36 + kc * 8 + tg + 4];
                mma_f16(s[nt], aq[kc], bfr);
            }
        }
#pragma unroll
        for (int nt = 0; nt < 8; nt++) {
            l0 += ex2(s[nt][0] * EXPC) + ex2(s[nt][1] * EXPC);
            l1 += ex2(s[nt][2] * EXPC) + ex2(s[nt][3] * EXPC);
        }
        __syncthreads();
    }

    l0 += __shfl_xor_sync(0xffffffffu, l0, 1);
    l0 += __shfl_xor_sync(0xffffffffu, l0, 2);
    l1 += __shfl_xor_sync(0xffffffffu, l1, 1);
    l1 += __shfl_xor_sync(0xffffffffu, l1, 2);
    const float li0 = -__log2f(l0);
    const float li1 = -__log2f(l1);

    // ================= pass 2: normalized P -> gmem, O += P*V =================
    stageK(0, 0);
    stageV(0, 0);
    cp_commit();

    float o[8][4];
#pragma unroll
    for (int nt = 0; nt < 8; nt++)
#pragma unroll
        for (int r = 0; r < 4; r++) o[nt][r] = 0.0f;

    float* a0base = attn + ((long long)bh * SS + qt * 128 + wrow + g) * SS + 2 * tg;

    for (int t = 0; t < 32; t++) {
        if (t < 31) { stageK(t + 1, (t + 1) & 1); stageV(t + 1, (t + 1) & 1); }
        cp_commit();
        cp_wait1();
        __syncthreads();

        const unsigned* kb = smw + 4608 + (t & 1) * 2304;
        const unsigned* vb = smw + 9216 + (t & 1) * 2304;

#pragma unroll
        for (int nt = 0; nt < 8; nt++)
#pragma unroll
            for (int r = 0; r < 4; r++) s[nt][r] = 0.0f;
#pragma unroll
        for (int kc = 0; kc < 4; kc++) {
#pragma unroll
            for (int nt = 0; nt < 8; nt++) {
                unsigned bfr[2];
                bfr[0] = kb[(nt * 8 + g) * 36 + kc * 8 + tg];
                bfr[1] = kb[(nt * 8 + g) * 36 + kc * 8 + tg + 4];
                mma_f16(s[nt], aq[kc], bfr);
            }
        }

        // exp + attn store
#pragma unroll
        for (int nt = 0; nt < 8; nt++) {
            s[nt][0] = ex2(fmaf(s[nt][0], EXPC, li0));
            s[nt][1] = ex2(fmaf(s[nt][1], EXPC, li0));
            s[nt][2] = ex2(fmaf(s[nt][2], EXPC, li1));
            s[nt][3] = ex2(fmaf(s[nt][3], EXPC, li1));
            float* ap = a0base + t * 64 + nt * 8;
            asm volatile("st.global.cs.v2.f32 [%0], {%1,%2};"
                         :: "l"(ap), "f"(s[nt][0]), "f"(s[nt][1]));
            asm volatile("st.global.cs.v2.f32 [%0], {%1,%2};"
                         :: "l"(ap + 8LL * SS), "f"(s[nt][2]), "f"(s[nt][3]));
        }

        // PV: P C-fragments ARE fp16 A-fragments (no shuffle needed)
#pragma unroll
        for (int u = 0; u < 4; u++) {
            unsigned pa[4];
            pa[0] = packh2(s[2 * u][0], s[2 * u][1]);
            pa[1] = packh2(s[2 * u][2], s[2 * u][3]);
            pa[2] = packh2(s[2 * u + 1][0], s[2 * u + 1][1]);
            pa[3] = packh2(s[2 * u + 1][2], s[2 * u + 1][3]);
#pragma unroll
            for (int nt2 = 0; nt2 < 8; nt2++) {
                unsigned bfr[2];
                bfr[0] = vb[(nt2 * 8 + g) * 36 + u * 8 + tg];
                bfr[1] = vb[(nt2 * 8 + g) * 36 + u * 8 + tg + 4];
                mma_f16(o[nt2], pa, bfr);
            }
        }
        __syncthreads();
    }

    // ---- O epilogue (context as fp16) ----
    __half* Cp = Cx + ((long long)b * SS + qt * 128 + wrow + g) * HH + h * HDD;
#pragma unroll
    for (int nt2 = 0; nt2 < 8; nt2++) {
        int col = nt2 * 8 + 2 * tg;
        *(__half2*)(Cp + col) = __floats2half2_rn(o[nt2][0], o[nt2][1]);
        *(__half2*)(Cp + 8LL * HH + col) = __floats2half2_rn(o[nt2][2], o[nt2][3]);
    }
}

// ---------------------------------------------------------------------------
extern "C" void kernel_launch(void* const* d_in, const int* in_sizes, int n_in,
                              void* d_out, int out_size)
{
    const float* query  = (const float*)d_in[0];
    const float* key_in = (const float*)d_in[1];
    const float* value  = (const float*)d_in[2];
    const float* Wq = (const float*)d_in[3];
    const float* bq = (const float*)d_in[4];
    const float* Wk = (const float*)d_in[5];
    const float* bk = (const float*)d_in[6];
    const float* Wv = (const float*)d_in[7];
    const float* bv = (const float*)d_in[8];
    const float* Wo = (const float*)d_in[9];
    const float* bo = (const float*)d_in[10];

    float* out  = (float*)d_out;                    // [B,S,H] fp32
    float* attn = out + (long long)BB * SS * HH;    // [B,NH,S,S] fp32

    __half *Qh, *Kh, *Vh, *Ch;
    cudaGetSymbolAddress((void**)&Qh, g_Qh);
    cudaGetSymbolAddress((void**)&Kh, g_Kh);
    cudaGetSymbolAddress((void**)&Vh, g_Vh);
    cudaGetSymbolAddress((void**)&Ch, g_Ch);

    cudaFuncSetAttribute(attn_fused,
                         cudaFuncAttributeMaxDynamicSharedMemorySize, FUSED_SMEM);

    dim3 pgrid(4, 64);   // N/128, M/128

    // projections: fp32 in -> fp16 out (V transposed to [b][h][d][s])
    gemm_f16<0, 1><<<pgrid, 256>>>(query,  Wq, bq, Qh);
    gemm_f16<0, 1><<<pgrid, 256>>>(key_in, Wk, bk, Kh);
    gemm_f16<0, 2><<<pgrid, 256>>>(value,  Wv, bv, Vh);

    // fused scores + softmax + context
    dim3 fgrid(SS / 128, BB * NHH);
    attn_fused<<<fgrid, 256, FUSED_SMEM>>>(Qh, Kh, Vh, attn, Ch);

    // output projection: fp16 in -> fp32 out
    gemm_f16<1, 0><<<pgrid, 256>>>(Ch, Wo, bo, out);
}

// round 8
// speedup vs baseline: 5.1764x; 1.2085x over previous
#include <cuda_runtime.h>
#include <cuda_fp16.h>
#include <cstdint>

#define BB 4
#define SS 2048
#define HH 512
#define NHH 8
#define HDD 64
#define EXPC 0.18033688011112042f   // log2(e)/8

// Scratch (device globals: no allocation allowed in kernel_launch)
__device__ __half g_INh[3u * BB * SS * HH];   // fp16 copies of query,key_in,value
__device__ __half g_Wh[4u * HH * HH];         // fp16 copies of Wq,Wk,Wv,Wo
__device__ __half g_Qh[BB * SS * HH];
__device__ __half g_Kh[BB * SS * HH];
__device__ __half g_Vh[BB * SS * HH];         // V^T: [b][h][d][s]
__device__ __half g_Ch[BB * SS * HH];         // context
__device__ float  g_L[BB * NHH * SS];         // softmax row sums

__device__ __forceinline__ float ex2(float x) {
    float y; asm("ex2.approx.ftz.f32 %0, %1;" : "=f"(y) : "f"(x)); return y;
}
__device__ __forceinline__ void cp16(unsigned dst, const void* src) {
    asm volatile("cp.async.cg.shared.global [%0], [%1], 16;" :: "r"(dst), "l"(src));
}
__device__ __forceinline__ void cp_commit() { asm volatile("cp.async.commit_group;"); }
__device__ __forceinline__ void cp_wait1() { asm volatile("cp.async.wait_group 1;"); }
__device__ __forceinline__ void cp_wait0() { asm volatile("cp.async.wait_group 0;"); }

__device__ __forceinline__ void mma_f16(float* c, const unsigned* a, const unsigned* b) {
    asm volatile(
        "mma.sync.aligned.m16n8k16.row.col.f32.f16.f16.f32 "
        "{%0,%1,%2,%3}, {%4,%5,%6,%7}, {%8,%9}, {%0,%1,%2,%3};"
        : "+f"(c[0]), "+f"(c[1]), "+f"(c[2]), "+f"(c[3])
        : "r"(a[0]), "r"(a[1]), "r"(a[2]), "r"(a[3]), "r"(b[0]), "r"(b[1]));
}
__device__ __forceinline__ void ldmx4(unsigned* r, unsigned addr) {
    asm volatile("ldmatrix.sync.aligned.m8n8.x4.shared.b16 {%0,%1,%2,%3}, [%4];"
                 : "=r"(r[0]), "=r"(r[1]), "=r"(r[2]), "=r"(r[3]) : "r"(addr));
}
__device__ __forceinline__ unsigned packh2(float lo, float hi) {
    __half2 h = __floats2half2_rn(lo, hi);
    return *(unsigned*)&h;
}

// ---------------------------------------------------------------------------
// fp32 -> fp16 conversion kernels
// ---------------------------------------------------------------------------
__global__ __launch_bounds__(256) void cvt_inputs(const float* __restrict__ q,
                                                  const float* __restrict__ k,
                                                  const float* __restrict__ v,
                                                  __half* __restrict__ dst)
{
    const float* s = blockIdx.y == 0 ? q : (blockIdx.y == 1 ? k : v);
    long long base = (long long)blockIdx.y * (BB * SS * HH);
    int idx = (blockIdx.x * 256 + threadIdx.x) * 4;
    float4 x = *(const float4*)(s + idx);
    __half2 h0 = __floats2half2_rn(x.x, x.y);
    __half2 h1 = __floats2half2_rn(x.z, x.w);
    uint2 u = make_uint2(*(unsigned*)&h0, *(unsigned*)&h1);
    *(uint2*)(dst + base + idx) = u;
}
__global__ __launch_bounds__(256) void cvt_w(const float* __restrict__ w0,
                                             const float* __restrict__ w1,
                                             const float* __restrict__ w2,
                                             const float* __restrict__ w3,
                                             __half* __restrict__ dst)
{
    const float* s = blockIdx.y == 0 ? w0 : (blockIdx.y == 1 ? w1 :
                     (blockIdx.y == 2 ? w2 : w3));
    long long base = (long long)blockIdx.y * (HH * HH);
    int idx = (blockIdx.x * 256 + threadIdx.x) * 4;
    float4 x = *(const float4*)(s + idx);
    __half2 h0 = __floats2half2_rn(x.x, x.y);
    __half2 h1 = __floats2half2_rn(x.z, x.w);
    uint2 u = make_uint2(*(unsigned*)&h0, *(unsigned*)&h1);
    *(uint2*)(dst + base + idx) = u;
}

// ---------------------------------------------------------------------------
// fp16 GEMM with cp.async double buffering: C[m,n] = sum_k A[m,k]*W[n,k] + b[n]
// M=8192, N=512, K=512. BM=BN=128, BK=32. 8 warps (2x4): WM64 x WN32.
// Each As/Bs buffer = 128 rows * 40 halfs * 2B = 10240 bytes.
// OUTMODE: 0 = fp32 row-major, 1 = fp16 row-major, 2 = fp16 transposed (V^T)
// ---------------------------------------------------------------------------
#define GBUF 10240

template <int OUTMODE>
__global__ __launch_bounds__(256, 2)
void gemm2(const __half* __restrict__ A, const __half* __restrict__ W,
           const float* __restrict__ bias, void* __restrict__ Cout)
{
    __shared__ __align__(16) __half As[2][128][40];
    __shared__ __align__(16) __half Bs[2][128][40];

    const unsigned sa = (unsigned)__cvta_generic_to_shared(&As[0][0][0]);
    const unsigned sbb = (unsigned)__cvta_generic_to_shared(&Bs[0][0][0]);

    const int bm = blockIdx.y * 128;
    const int bn = blockIdx.x * 128;
    const int tid = threadIdx.x;
    const int warpId = tid >> 5, lane = tid & 31;
    const int g = lane >> 2, tg = lane & 3;
    const int wm = warpId >> 2;
    const int wn = warpId & 3;

    auto stage = [&](int kt, int buf) {
#pragma unroll
        for (int it = 0; it < 2; it++) {
            int idx = tid + it * 256;
            int row = idx >> 2, seg = idx & 3;
            cp16(sa + buf * GBUF + row * 80 + seg * 16,
                 A + (long long)(bm + row) * 512 + kt * 32 + seg * 8);
            cp16(sbb + buf * GBUF + row * 80 + seg * 16,
                 W + (long long)(bn + row) * 512 + kt * 32 + seg * 8);
        }
    };

    float c[4][4][4];
#pragma unroll
    for (int i = 0; i < 4; i++)
#pragma unroll
        for (int j = 0; j < 4; j++)
#pragma unroll
            for (int r = 0; r < 4; r++) c[i][j][r] = 0.0f;

    stage(0, 0);
    cp_commit();

    for (int kt = 0; kt < 16; kt++) {
        if (kt < 15) stage(kt + 1, (kt + 1) & 1);
        cp_commit();
        cp_wait1();
        __syncthreads();

        const unsigned* Asw = (const unsigned*)&As[kt & 1][0][0];
        const unsigned* Bsw = (const unsigned*)&Bs[kt & 1][0][0];
#pragma unroll
        for (int kc = 0; kc < 2; kc++) {
            unsigned a[4][4], b[4][2];
#pragma unroll
            for (int mt = 0; mt < 4; mt++) {
                int row = wm * 64 + mt * 16 + g;
                a[mt][0] = Asw[row * 20 + kc * 8 + tg];
                a[mt][1] = Asw[(row + 8) * 20 + kc * 8 + tg];
                a[mt][2] = Asw[row * 20 + kc * 8 + tg + 4];
                a[mt][3] = Asw[(row + 8) * 20 + kc * 8 + tg + 4];
            }
#pragma unroll
            for (int nt = 0; nt < 4; nt++) {
                int col = wn * 32 + nt * 8 + g;
                b[nt][0] = Bsw[col * 20 + kc * 8 + tg];
                b[nt][1] = Bsw[col * 20 + kc * 8 + tg + 4];
            }
#pragma unroll
            for (int mt = 0; mt < 4; mt++)
#pragma unroll
                for (int nt = 0; nt < 4; nt++)
                    mma_f16(c[mt][nt], a[mt], b[nt]);
        }
        __syncthreads();
    }

#pragma unroll
    for (int mt = 0; mt < 4; mt++) {
#pragma unroll
        for (int nt = 0; nt < 4; nt++) {
            int row = bm + wm * 64 + mt * 16 + g;
            int col = bn + wn * 32 + nt * 8 + 2 * tg;
            float bx = bias[col], by = bias[col + 1];
            float o0 = c[mt][nt][0] + bx, o1 = c[mt][nt][1] + by;
            float o2 = c[mt][nt][2] + bx, o3 = c[mt][nt][3] + by;
            if (OUTMODE == 0) {
                float* Cf = (float*)Cout;
                *(float2*)(Cf + (long long)row * 512 + col) = make_float2(o0, o1);
                *(float2*)(Cf + (long long)(row + 8) * 512 + col) = make_float2(o2, o3);
            } else if (OUTMODE == 1) {
                __half* Ch = (__half*)Cout;
                *(__half2*)(Ch + (long long)row * 512 + col) = __floats2half2_rn(o0, o1);
                *(__half2*)(Ch + (long long)(row + 8) * 512 + col) = __floats2half2_rn(o2, o3);
            } else {
                __half* Ch = (__half*)Cout;
                int bo = row >> 11, so = row & 2047;
                int ho = col >> 6, dd = col & 63;
                long long base = (((long long)bo * NHH + ho) * HDD + dd) * SS + so;
                Ch[base]          = __float2half_rn(o0);
                Ch[base + SS]     = __float2half_rn(o1);
                Ch[base + 8]      = __float2half_rn(o2);
                Ch[base + SS + 8] = __float2half_rn(o3);
            }
        }
    }
}

// ---------------------------------------------------------------------------
// Fused attention, split into two kernels. 256 threads (8 warps), Q tile =
// 256 rows (32/warp, MT=2), K/V tiles 64 rows double-buffered.
// smem layout (bytes): Q at 0 (256*144), K at 36864 (2 bufs * 9216),
//                      V at 55296 (2 bufs * 9216, pass2 only)
// ---------------------------------------------------------------------------
#define QOFF 0
#define KOFF 36864
#define VOFF 55296
#define P1_SMEM 55296
#define P2_SMEM 73728

// ---- pass 1: l[row] = sum_k exp2(s * EXPC) ----
__global__ __launch_bounds__(256, 2)
void attn_pass1(const __half* __restrict__ Q, const __half* __restrict__ K,
                float* __restrict__ L)
{
    extern __shared__ __align__(16) unsigned char smraw[];
    const unsigned sb = (unsigned)__cvta_generic_to_shared(smraw);

    const int tid = threadIdx.x;
    const int wid = tid >> 5, lane = tid & 31;
    const int g = lane >> 2, tg = lane & 3;
    const int wrow = wid * 32;

    const int qt = blockIdx.x, bh = blockIdx.y;
    const int b = bh >> 3, h = bh & 7;

    const __half* Qg = Q + ((long long)b * SS + qt * 256) * HH + h * HDD;
    const __half* Kg = K + (long long)b * SS * HH + h * HDD;

    auto stageK = [&](int t, int buf) {
#pragma unroll
        for (int i = 0; i < 2; i++) {
            int idx = tid + i * 256;
            int row = idx >> 3, seg = idx & 7;
            cp16(sb + KOFF + buf * 9216 + row * 144 + seg * 16,
                 Kg + (long long)(t * 64 + row) * HH + seg * 8);
        }
    };

    // stage Q (256 rows) + K tile 0
#pragma unroll
    for (int i = 0; i < 8; i++) {
        int idx = tid + i * 256;
        int row = idx >> 3, seg = idx & 7;
        cp16(sb + QOFF + row * 144 + seg * 16, Qg + (long long)row * HH + seg * 8);
    }
    stageK(0, 0);
    cp_commit();
    cp_wait0();
    __syncthreads();

    // persistent Q A-fragments via ldmatrix
    const unsigned qloff = (lane & 15) * 144 + (lane >> 4) * 16;
    unsigned aq[2][4][4];
#pragma unroll
    for (int mt = 0; mt < 2; mt++)
#pragma unroll
        for (int kc = 0; kc < 4; kc++)
            ldmx4(aq[mt][kc], sb + QOFF + (wrow + mt * 16) * 144 + kc * 32 + qloff);

    const unsigned loff = ((lane >> 4) * 8 + (lane & 7)) * 144 + ((lane >> 3) & 1) * 16;

    float l[2][2] = {{0.0f, 0.0f}, {0.0f, 0.0f}};

    for (int t = 0; t < 32; t++) {
        if (t < 31) stageK(t + 1, (t + 1) & 1);
        cp_commit();
        cp_wait1();
        __syncthreads();

        const unsigned kb = sb + KOFF + (t & 1) * 9216;
#pragma unroll
        for (int ch = 0; ch < 4; ch++) {
            float s[2][2][4];
#pragma unroll
            for (int mt = 0; mt < 2; mt++)
#pragma unroll
                for (int j = 0; j < 2; j++)
#pragma unroll
                    for (int r = 0; r < 4; r++) s[mt][j][r] = 0.0f;
#pragma unroll
            for (int kc = 0; kc < 4; kc++) {
                unsigned kf[4];
                ldmx4(kf, kb + ch * 2304 + kc * 32 + loff);
                mma_f16(s[0][0], aq[0][kc], kf);
                mma_f16(s[0][1], aq[0][kc], kf + 2);
                mma_f16(s[1][0], aq[1][kc], kf);
                mma_f16(s[1][1], aq[1][kc], kf + 2);
            }
#pragma unroll
            for (int mt = 0; mt < 2; mt++)
#pragma unroll
                for (int j = 0; j < 2; j++) {
                    l[mt][0] += ex2(s[mt][j][0] * EXPC) + ex2(s[mt][j][1] * EXPC);
                    l[mt][1] += ex2(s[mt][j][2] * EXPC) + ex2(s[mt][j][3] * EXPC);
                }
        }
        __syncthreads();
    }

#pragma unroll
    for (int mt = 0; mt < 2; mt++)
#pragma unroll
        for (int hh = 0; hh < 2; hh++) {
            float v = l[mt][hh];
            v += __shfl_xor_sync(0xffffffffu, v, 1);
            v += __shfl_xor_sync(0xffffffffu, v, 2);
            if (tg == 0)
                L[(long long)bh * SS + qt * 256 + wrow + mt * 16 + hh * 8 + g] = v;
        }
}

// ---- pass 2: p = 2^(s*EXPC - log2 l) -> attn gmem; O += P*V ----
__global__ __launch_bounds__(256, 2)
void attn_pass2(const __half* __restrict__ Q, const __half* __restrict__ K,
                const __half* __restrict__ V, const float* __restrict__ L,
                float* __restrict__ attn, __half* __restrict__ Cx)
{
    extern __shared__ __align__(16) unsigned char smraw[];
    const unsigned sb = (unsigned)__cvta_generic_to_shared(smraw);

    const int tid = threadIdx.x;
    const int wid = tid >> 5, lane = tid & 31;
    const int g = lane >> 2, tg = lane & 3;
    const int wrow = wid * 32;

    const int qt = blockIdx.x, bh = blockIdx.y;
    const int b = bh >> 3, h = bh & 7;

    const __half* Qg = Q + ((long long)b * SS + qt * 256) * HH + h * HDD;
    const __half* Kg = K + (long long)b * SS * HH + h * HDD;
    const __half* Vg = V + (long long)bh * HDD * SS;

    auto stageK = [&](int t, int buf) {
#pragma unroll
        for (int i = 0; i < 2; i++) {
            int idx = tid + i * 256;
            int row = idx >> 3, seg = idx & 7;
            cp16(sb + KOFF + buf * 9216 + row * 144 + seg * 16,
                 Kg + (long long)(t * 64 + row) * HH + seg * 8);
        }
    };
    auto stageV = [&](int t, int buf) {
#pragma unroll
        for (int i = 0; i < 2; i++) {
            int idx = tid + i * 256;
            int row = idx >> 3, seg = idx & 7;   // row = d index
            cp16(sb + VOFF + buf * 9216 + row * 144 + seg * 16,
                 Vg + (long long)row * SS + t * 64 + seg * 8);
        }
    };

#pragma unroll
    for (int i = 0; i < 8; i++) {
        int idx = tid + i * 256;
        int row = idx >> 3, seg = idx & 7;
        cp16(sb + QOFF + row * 144 + seg * 16, Qg + (long long)row * HH + seg * 8);
    }
    stageK(0, 0);
    stageV(0, 0);
    cp_commit();
    cp_wait0();
    __syncthreads();

    const unsigned qloff = (lane & 15) * 144 + (lane >> 4) * 16;
    unsigned aq[2][4][4];
#pragma unroll
    for (int mt = 0; mt < 2; mt++)
#pragma unroll
        for (int kc = 0; kc < 4; kc++)
            ldmx4(aq[mt][kc], sb + QOFF + (wrow + mt * 16) * 144 + kc * 32 + qloff);

    const unsigned loff = ((lane >> 4) * 8 + (lane & 7)) * 144 + ((lane >> 3) & 1) * 16;

    float li[2][2];
#pragma unroll
    for (int mt = 0; mt < 2; mt++)
#pragma unroll
        for (int hh = 0; hh < 2; hh++)
            li[mt][hh] = -__log2f(L[(long long)bh * SS + qt * 256 + wrow + mt * 16 + hh * 8 + g]);

    float o[2][8][4];
#pragma unroll
    for (int mt = 0; mt < 2; mt++)
#pragma unroll
        for (int nt = 0; nt < 8; nt++)
#pragma unroll
            for (int r = 0; r < 4; r++) o[mt][nt][r] = 0.0f;

    float* attnBase = attn + ((long long)bh * SS + qt * 256 + wrow + g) * SS;

    for (int t = 0; t < 32; t++) {
        if (t < 31) { stageK(t + 1, (t + 1) & 1); stageV(t + 1, (t + 1) & 1); }
        cp_commit();
        cp_wait1();
        __syncthreads();

        const unsigned kb = sb + KOFF + (t & 1) * 9216;
        const unsigned vb = sb + VOFF + (t & 1) * 9216;

#pragma unroll
        for (int ch = 0; ch < 4; ch++) {
            float s[2][2][4];
#pragma unroll
            for (int mt = 0; mt < 2; mt++)
#pragma unroll
                for (int j = 0; j < 2; j++)
#pragma unroll
                    for (int r = 0; r < 4; r++) s[mt][j][r] = 0.0f;
#pragma unroll
            for (int kc = 0; kc < 4; kc++) {
                unsigned kf[4];
                ldmx4(kf, kb + ch * 2304 + kc * 32 + loff);
                mma_f16(s[0][0], aq[0][kc], kf);
                mma_f16(s[0][1], aq[0][kc], kf + 2);
                mma_f16(s[1][0], aq[1][kc], kf);
                mma_f16(s[1][1], aq[1][kc], kf + 2);
            }

            unsigned pa[2][4];
#pragma unroll
            for (int mt = 0; mt < 2; mt++) {
#pragma unroll
                for (int j = 0; j < 2; j++) {
                    s[mt][j][0] = ex2(fmaf(s[mt][j][0], EXPC, li[mt][0]));
                    s[mt][j][1] = ex2(fmaf(s[mt][j][1], EXPC, li[mt][0]));
                    s[mt][j][2] = ex2(fmaf(s[mt][j][2], EXPC, li[mt][1]));
                    s[mt][j][3] = ex2(fmaf(s[mt][j][3], EXPC, li[mt][1]));
                }
                float* ap = attnBase + (long long)(mt * 16) * SS + t * 64 + ch * 16 + 2 * tg;
                asm volatile("st.global.cs.v2.f32 [%0], {%1,%2};"
                             :: "l"(ap), "f"(s[mt][0][0]), "f"(s[mt][0][1]));
                asm volatile("st.global.cs.v2.f32 [%0], {%1,%2};"
                             :: "l"(ap + 8), "f"(s[mt][1][0]), "f"(s[mt][1][1]));
                asm volatile("st.global.cs.v2.f32 [%0], {%1,%2};"
                             :: "l"(ap + 8LL * SS), "f"(s[mt][0][2]), "f"(s[mt][0][3]));
                asm volatile("st.global.cs.v2.f32 [%0], {%1,%2};"
                             :: "l"(ap + 8LL * SS + 8), "f"(s[mt][1][2]), "f"(s[mt][1][3]));
                pa[mt][0] = packh2(s[mt][0][0], s[mt][0][1]);
                pa[mt][1] = packh2(s[mt][0][2], s[mt][0][3]);
                pa[mt][2] = packh2(s[mt][1][0], s[mt][1][1]);
                pa[mt][3] = packh2(s[mt][1][2], s[mt][1][3]);
            }

#pragma unroll
            for (int np = 0; np < 4; np++) {
                unsigned vf[4];
                ldmx4(vf, vb + np * 2304 + ch * 32 + loff);
                mma_f16(o[0][2 * np],     pa[0], vf);
                mma_f16(o[0][2 * np + 1], pa[0], vf + 2);
                mma_f16(o[1][2 * np],     pa[1], vf);
                mma_f16(o[1][2 * np + 1], pa[1], vf + 2);
            }
        }
        __syncthreads();
    }

    // O epilogue (context fp16)
    __half* Cp = Cx + ((long long)b * SS + qt * 256 + wrow + g) * HH + h * HDD;
#pragma unroll
    for (int mt = 0; mt < 2; mt++)
#pragma unroll
        for (int nt = 0; nt < 8; nt++) {
            int col = nt * 8 + 2 * tg;
            *(__half2*)(Cp + (long long)(mt * 16) * HH + col) =
                __floats2half2_rn(o[mt][nt][0], o[mt][nt][1]);
            *(__half2*)(Cp + (long long)(mt * 16 + 8) * HH + col) =
                __floats2half2_rn(o[mt][nt][2], o[mt][nt][3]);
        }
}

// ---------------------------------------------------------------------------
extern "C" void kernel_launch(void* const* d_in, const int* in_sizes, int n_in,
                              void* d_out, int out_size)
{
    const float* query  = (const float*)d_in[0];
    const float* key_in = (const float*)d_in[1];
    const float* value  = (const float*)d_in[2];
    const float* Wq = (const float*)d_in[3];
    const float* bq = (const float*)d_in[4];
    const float* Wk = (const float*)d_in[5];
    const float* bk = (const float*)d_in[6];
    const float* Wv = (const float*)d_in[7];
    const float* bv = (const float*)d_in[8];
    const float* Wo = (const float*)d_in[9];
    const float* bo = (const float*)d_in[10];

    float* out  = (float*)d_out;
    float* attn = out + (long long)BB * SS * HH;

    __half *INh, *Wh, *Qh, *Kh, *Vh, *Ch;
    float* L;
    cudaGetSymbolAddress((void**)&INh, g_INh);
    cudaGetSymbolAddress((void**)&Wh, g_Wh);
    cudaGetSymbolAddress((void**)&Qh, g_Qh);
    cudaGetSymbolAddress((void**)&Kh, g_Kh);
    cudaGetSymbolAddress((void**)&Vh, g_Vh);
    cudaGetSymbolAddress((void**)&Ch, g_Ch);
    cudaGetSymbolAddress((void**)&L, g_L);

    cudaFuncSetAttribute(attn_pass1, cudaFuncAttributeMaxDynamicSharedMemorySize, P1_SMEM);
    cudaFuncSetAttribute(attn_pass2, cudaFuncAttributeMaxDynamicSharedMemorySize, P2_SMEM);

    // fp32 -> fp16 conversions
    cvt_inputs<<<dim3(4096, 3), 256>>>(query, key_in, value, INh);
    cvt_w<<<dim3(256, 4), 256>>>(Wq, Wk, Wv, Wo, Wh);

    // projections
    dim3 pgrid(4, 64);
    gemm2<1><<<pgrid, 256>>>(INh,                Wh,               bq, Qh);
    gemm2<1><<<pgrid, 256>>>(INh + BB * SS * HH, Wh + HH * HH,     bk, Kh);
    gemm2<2><<<pgrid, 256>>>(INh + 2u * BB * SS * HH, Wh + 2u * HH * HH, bv, Vh);

    // fused attention (two passes)
    dim3 fgrid(SS / 256, BB * NHH);
    attn_pass1<<<fgrid, 256, P1_SMEM>>>(Qh, Kh, L);
    attn_pass2<<<fgrid, 256, P2_SMEM>>>(Qh, Kh, Vh, L, attn, Ch);

    // output projection
    gemm2<0><<<pgrid, 256>>>(Ch, Wh + 3u * HH * HH, bo, out);
}